// round 3
// baseline (speedup 1.0000x reference)
#include <cuda_runtime.h>
#include <math.h>

#define B_   4
#define S_   2048
#define DM   512
#define NH   8
#define DH   64
#define SCALE 0.044194173824159216f  // 1/sqrt(512)

// Scratch (device globals — no allocation allowed)
__device__ float g_Q[B_ * NH * S_ * DH];     // 16 MB, [b,h,s,dh]
__device__ float g_K[B_ * NH * S_ * DH];     // 16 MB
__device__ float g_V[B_ * NH * S_ * DH];     // 16 MB
__device__ float g_att[B_ * S_ * DM];        // 16 MB, [b,s,h*dh]

// ---------------------------------------------------------------------------
// Fused QKV GEMM: for one 64x64 output tile position, compute
//   Q = x@Wq + bq, K = x@Wk + bk, V = x@Wv + bv
// sharing the A (x) tile. 256 threads, 4x4 micro-tile per thread per matrix.
// Outputs written head-split: [b,h,s,dh].
// ---------------------------------------------------------------------------
__global__ __launch_bounds__(256) void qkv_gemm_kernel(
    const float* __restrict__ A,
    const float* __restrict__ Wq, const float* __restrict__ bq,
    const float* __restrict__ Wk, const float* __restrict__ bk,
    const float* __restrict__ Wv, const float* __restrict__ bv,
    float* __restrict__ outQ, float* __restrict__ outK, float* __restrict__ outV)
{
    __shared__ float As [16][68];   // [k][m], padded
    __shared__ float Bqs[16][64];   // [k][n]
    __shared__ float Bks[16][64];
    __shared__ float Bvs[16][64];

    const int t  = threadIdx.x;
    const int tx = t & 15;
    const int ty = t >> 4;
    const int m0 = blockIdx.y * 64;
    const int n0 = blockIdx.x * 64;

    float aq[4][4] = {}, ak[4][4] = {}, av_[4][4] = {};

    for (int k0 = 0; k0 < DM; k0 += 16) {
        // A tile (64 x 16): thread t -> m = t>>2, kq = t&3 (float4 along k)
        {
            int m  = t >> 2;
            int kq = t & 3;
            float4 a4 = *(const float4*)&A[(size_t)(m0 + m) * DM + k0 + kq * 4];
            As[kq * 4 + 0][m] = a4.x;
            As[kq * 4 + 1][m] = a4.y;
            As[kq * 4 + 2][m] = a4.z;
            As[kq * 4 + 3][m] = a4.w;
        }
        // W tiles (16 x 64): k = t>>4, n4 = t&15
        {
            int k  = t >> 4;
            int n4 = t & 15;
            size_t off = (size_t)(k0 + k) * DM + n0 + n4 * 4;
            *(float4*)&Bqs[k][n4 * 4] = *(const float4*)&Wq[off];
            *(float4*)&Bks[k][n4 * 4] = *(const float4*)&Wk[off];
            *(float4*)&Bvs[k][n4 * 4] = *(const float4*)&Wv[off];
        }
        __syncthreads();

        #pragma unroll
        for (int kk = 0; kk < 16; kk++) {
            float4 a4 = *(const float4*)&As [kk][ty * 4];
            float4 q4 = *(const float4*)&Bqs[kk][tx * 4];
            float4 k4 = *(const float4*)&Bks[kk][tx * 4];
            float4 v4 = *(const float4*)&Bvs[kk][tx * 4];
            float avv[4] = {a4.x, a4.y, a4.z, a4.w};
            float qv[4]  = {q4.x, q4.y, q4.z, q4.w};
            float kv[4]  = {k4.x, k4.y, k4.z, k4.w};
            float vv[4]  = {v4.x, v4.y, v4.z, v4.w};
            #pragma unroll
            for (int i = 0; i < 4; i++)
                #pragma unroll
                for (int j = 0; j < 4; j++) {
                    aq [i][j] = fmaf(avv[i], qv[j], aq [i][j]);
                    ak [i][j] = fmaf(avv[i], kv[j], ak [i][j]);
                    av_[i][j] = fmaf(avv[i], vv[j], av_[i][j]);
                }
        }
        __syncthreads();
    }

    // Epilogue: head-split layout [b,h,s,dh]
    #pragma unroll
    for (int i = 0; i < 4; i++) {
        int row = m0 + ty * 4 + i;
        int b   = row / S_;
        int s   = row % S_;
        #pragma unroll
        for (int j = 0; j < 4; j++) {
            int col = n0 + tx * 4 + j;
            int h   = col >> 6;
            int dh  = col & 63;
            size_t o = (size_t)((b * NH + h) * S_ + s) * DH + dh;
            outQ[o] = aq [i][j] + bq[col];
            outK[o] = ak [i][j] + bk[col];
            outV[o] = av_[i][j] + bv[col];
        }
    }
}

// ---------------------------------------------------------------------------
// Plain tiled GEMM for the output projection: C = A@W + bias, row-major out.
// ---------------------------------------------------------------------------
__global__ __launch_bounds__(256) void gemm_kernel(
    const float* __restrict__ A,
    const float* __restrict__ W,
    const float* __restrict__ bias,
    float* __restrict__ out)
{
    __shared__ float As[16][68];
    __shared__ float Bs[16][64];

    const int t  = threadIdx.x;
    const int tx = t & 15;
    const int ty = t >> 4;
    const int m0 = blockIdx.y * 64;
    const int n0 = blockIdx.x * 64;

    float acc[4][4] = {};

    for (int k0 = 0; k0 < DM; k0 += 16) {
        {
            int m  = t >> 2;
            int kq = t & 3;
            float4 a4 = *(const float4*)&A[(size_t)(m0 + m) * DM + k0 + kq * 4];
            As[kq * 4 + 0][m] = a4.x;
            As[kq * 4 + 1][m] = a4.y;
            As[kq * 4 + 2][m] = a4.z;
            As[kq * 4 + 3][m] = a4.w;
        }
        {
            int k  = t >> 4;
            int n4 = t & 15;
            *(float4*)&Bs[k][n4 * 4] =
                *(const float4*)&W[(size_t)(k0 + k) * DM + n0 + n4 * 4];
        }
        __syncthreads();

        #pragma unroll
        for (int kk = 0; kk < 16; kk++) {
            float4 a4 = *(const float4*)&As[kk][ty * 4];
            float4 b4 = *(const float4*)&Bs[kk][tx * 4];
            float avv[4] = {a4.x, a4.y, a4.z, a4.w};
            float bv[4]  = {b4.x, b4.y, b4.z, b4.w};
            #pragma unroll
            for (int i = 0; i < 4; i++)
                #pragma unroll
                for (int j = 0; j < 4; j++)
                    acc[i][j] = fmaf(avv[i], bv[j], acc[i][j]);
        }
        __syncthreads();
    }

    #pragma unroll
    for (int i = 0; i < 4; i++) {
        int row = m0 + ty * 4 + i;
        #pragma unroll
        for (int j = 0; j < 4; j++) {
            int col = n0 + tx * 4 + j;
            out[(size_t)row * DM + col] = acc[i][j] + bias[col];
        }
    }
}

// ---------------------------------------------------------------------------
// Flash attention: one block = (b,h) x 64-query tile; iterate 64-key tiles.
// 256 threads as 16x16; thread (ty,tx) owns queries ty*4..+3, dims/keys tx*4..+3.
// Online softmax; P stored transposed [k][q] for conflict-free PV GEMM.
// Row stats replicated across 16 tx-threads via shfl (same half-warp).
// ---------------------------------------------------------------------------
#define FLASH_SMEM (4 * 64 * 68 * 4)   // Qt, Kt, Vs, Pt : 69632 bytes

__global__ __launch_bounds__(256) void flash_kernel()
{
    extern __shared__ float sm[];
    float* Qt = sm;                 // [d][m]  64x68
    float* Kt = Qt + 64 * 68;       // [d][k]  64x68
    float* Vs = Kt + 64 * 68;       // [k][d]  64x68
    float* Pt = Vs + 64 * 68;       // [k][q]  64x68

    const int t  = threadIdx.x;
    const int tx = t & 15;
    const int ty = t >> 4;
    const int q0 = blockIdx.x * 64;
    const int bh = blockIdx.y;                 // b*NH + h

    const float* __restrict__ Qb = g_Q + (size_t)bh * S_ * DH;
    const float* __restrict__ Kb = g_K + (size_t)bh * S_ * DH;
    const float* __restrict__ Vb = g_V + (size_t)bh * S_ * DH;

    // Load Q tile transposed: Qt[d][m]
    #pragma unroll
    for (int i = 0; i < 4; i++) {
        int e  = t + i * 256;        // float4 index 0..1023
        int m  = e >> 4;
        int dq = e & 15;
        float4 q4 = *(const float4*)&Qb[(size_t)(q0 + m) * DH + dq * 4];
        int d = dq * 4;
        Qt[(d + 0) * 68 + m] = q4.x;
        Qt[(d + 1) * 68 + m] = q4.y;
        Qt[(d + 2) * 68 + m] = q4.z;
        Qt[(d + 3) * 68 + m] = q4.w;
    }

    float m_run[4], l_run[4];
    float o[4][4] = {};
    #pragma unroll
    for (int i = 0; i < 4; i++) { m_run[i] = -1e30f; l_run[i] = 0.0f; }

    __syncthreads();

    for (int kt = 0; kt < S_; kt += 64) {
        __syncthreads();   // prior iteration's reads of Kt/Vs/Pt complete

        // Load K transposed + V straight
        #pragma unroll
        for (int i = 0; i < 4; i++) {
            int e  = t + i * 256;
            int m  = e >> 4;
            int dq = e & 15;
            float4 k4 = *(const float4*)&Kb[(size_t)(kt + m) * DH + dq * 4];
            int d = dq * 4;
            Kt[(d + 0) * 68 + m] = k4.x;
            Kt[(d + 1) * 68 + m] = k4.y;
            Kt[(d + 2) * 68 + m] = k4.z;
            Kt[(d + 3) * 68 + m] = k4.w;
            *(float4*)&Vs[m * 68 + d] =
                *(const float4*)&Vb[(size_t)(kt + m) * DH + dq * 4];
        }
        __syncthreads();

        // scores: s[i][j] = Q[qy] . K[kx]
        float s[4][4] = {};
        #pragma unroll 8
        for (int d = 0; d < DH; d++) {
            float4 qa = *(const float4*)&Qt[d * 68 + ty * 4];
            float4 kb = *(const float4*)&Kt[d * 68 + tx * 4];
            float qv[4] = {qa.x, qa.y, qa.z, qa.w};
            float kv[4] = {kb.x, kb.y, kb.z, kb.w};
            #pragma unroll
            for (int i = 0; i < 4; i++)
                #pragma unroll
                for (int j = 0; j < 4; j++)
                    s[i][j] = fmaf(qv[i], kv[j], s[i][j]);
        }

        // online softmax (row reductions over the 16 tx threads)
        float p[4][4];
        #pragma unroll
        for (int i = 0; i < 4; i++) {
            float r = -1e30f;
            #pragma unroll
            for (int j = 0; j < 4; j++) {
                s[i][j] *= SCALE;
                r = fmaxf(r, s[i][j]);
            }
            #pragma unroll
            for (int off = 8; off > 0; off >>= 1)
                r = fmaxf(r, __shfl_xor_sync(0xffffffffu, r, off));
            float mn   = fmaxf(m_run[i], r);
            float corr = __expf(m_run[i] - mn);
            float rs   = 0.0f;
            #pragma unroll
            for (int j = 0; j < 4; j++) {
                p[i][j] = __expf(s[i][j] - mn);
                rs += p[i][j];
            }
            #pragma unroll
            for (int off = 8; off > 0; off >>= 1)
                rs += __shfl_xor_sync(0xffffffffu, rs, off);
            l_run[i] = l_run[i] * corr + rs;
            m_run[i] = mn;
            #pragma unroll
            for (int j = 0; j < 4; j++) o[i][j] *= corr;
        }

        // Store P transposed: Pt[k][q]
        #pragma unroll
        for (int j = 0; j < 4; j++) {
            float4 w = make_float4(p[0][j], p[1][j], p[2][j], p[3][j]);
            *(float4*)&Pt[(tx * 4 + j) * 68 + ty * 4] = w;
        }
        __syncthreads();

        // PV GEMM: o[i][j] += sum_k P[q][k] * V[k][d]
        #pragma unroll 8
        for (int kk = 0; kk < 64; kk++) {
            float4 p4 = *(const float4*)&Pt[kk * 68 + ty * 4];
            float4 v4 = *(const float4*)&Vs[kk * 68 + tx * 4];
            float pv[4] = {p4.x, p4.y, p4.z, p4.w};
            float vv[4] = {v4.x, v4.y, v4.z, v4.w};
            #pragma unroll
            for (int i = 0; i < 4; i++)
                #pragma unroll
                for (int j = 0; j < 4; j++)
                    o[i][j] = fmaf(pv[i], vv[j], o[i][j]);
        }
    }

    // Normalize + write merged-head layout [b, s, h*64 + d]
    const int b = bh >> 3;
    const int h = bh & 7;
    #pragma unroll
    for (int i = 0; i < 4; i++) {
        int q = q0 + ty * 4 + i;
        float invl = 1.0f / l_run[i];
        float4 ov = make_float4(o[i][0] * invl, o[i][1] * invl,
                                o[i][2] * invl, o[i][3] * invl);
        *(float4*)&g_att[(size_t)(b * S_ + q) * DM + h * DH + tx * 4] = ov;
    }
}

// ---------------------------------------------------------------------------
extern "C" void kernel_launch(void* const* d_in, const int* in_sizes, int n_in,
                              void* d_out, int out_size)
{
    const float* x  = (const float*)d_in[0];
    const float* Wq = (const float*)d_in[1];
    const float* bq = (const float*)d_in[2];
    const float* Wk = (const float*)d_in[3];
    const float* bk = (const float*)d_in[4];
    const float* Wv = (const float*)d_in[5];
    const float* bv = (const float*)d_in[6];
    const float* Wo = (const float*)d_in[7];
    const float* bo = (const float*)d_in[8];
    float* out = (float*)d_out;

    void *pQ, *pK, *pV, *pA;
    cudaGetSymbolAddress(&pQ, g_Q);
    cudaGetSymbolAddress(&pK, g_K);
    cudaGetSymbolAddress(&pV, g_V);
    cudaGetSymbolAddress(&pA, g_att);

    cudaFuncSetAttribute(flash_kernel,
                         cudaFuncAttributeMaxDynamicSharedMemorySize, FLASH_SMEM);

    dim3 ggrid(DM / 64, (B_ * S_) / 64);   // (8, 128)

    qkv_gemm_kernel<<<ggrid, 256>>>(x, Wq, bq, Wk, bk, Wv, bv,
                                    (float*)pQ, (float*)pK, (float*)pV);

    flash_kernel<<<dim3(S_ / 64, B_ * NH), 256, FLASH_SMEM>>>();

    gemm_kernel<<<ggrid, 256>>>((const float*)pA, Wo, bo, out);
}

// round 7
// speedup vs baseline: 1.3345x; 1.3345x over previous
#include <cuda_runtime.h>
#include <math.h>
#include <stdint.h>

#define B_   4
#define S_   2048
#define DM   512
#define NH   8
#define DH   64
#define SCALE 0.044194173824159216f  // 1/sqrt(512)

// Scratch (device globals — no allocation allowed)
__device__ float g_Q[B_ * NH * S_ * DH];     // [b,h,s,dh]
__device__ float g_K[B_ * NH * S_ * DH];
__device__ float g_V[B_ * NH * S_ * DH];
__device__ float g_att[B_ * S_ * DM];        // [b,s,h*dh]

// ---------------------------------------------------------------------------
// tf32 helpers
// ---------------------------------------------------------------------------
__device__ __forceinline__ float to_tf32(float x) {
    uint32_t u;
    asm("cvt.rna.tf32.f32 %0, %1;" : "=r"(u) : "f"(x));
    return __uint_as_float(u);
}

// D += A(16x8) * B(8x8), tf32 inputs, f32 accumulate.
__device__ __forceinline__ void mma8(float d[4], const float a[4], const float b[2]) {
    uint32_t const* A = reinterpret_cast<uint32_t const*>(a);
    uint32_t const* Bf = reinterpret_cast<uint32_t const*>(b);
    asm volatile(
        "mma.sync.aligned.m16n8k8.row.col.f32.tf32.tf32.f32 "
        "{%0,%1,%2,%3}, {%4,%5,%6,%7}, {%8,%9}, {%0,%1,%2,%3};"
        : "+f"(d[0]), "+f"(d[1]), "+f"(d[2]), "+f"(d[3])
        : "r"(A[0]), "r"(A[1]), "r"(A[2]), "r"(A[3]),
          "r"(Bf[0]), "r"(Bf[1]));
}

// ---------------------------------------------------------------------------
// GEMM via mma.sync: C[M,512] = A[M,512] @ W[512,512] + bias
// BM=128, BN=64, BK=32. 256 threads = 8 warps in 4x2 (warp tile 32x32).
// SPLIT: 2-term tf32 decomposition (drops only lo*lo). HEAD_SPLIT: write
// [b,h,s,dh] layout.
// smem layout (dynamic): Ah[32][132], (Al), Wh[32][68], (Wl)
// ---------------------------------------------------------------------------
#define GEMM_SMEM(SPLIT) ((SPLIT ? 2 : 1) * (32*132 + 32*68) * 4)

template <bool SPLIT, bool HEAD_SPLIT>
__global__ __launch_bounds__(256) void mma_gemm(
    const float* __restrict__ A,
    const float* __restrict__ W,
    const float* __restrict__ bias,
    float* __restrict__ out)
{
    extern __shared__ float sm[];
    float* Ah = sm;
    float* Al = SPLIT ? (Ah + 32*132) : Ah;
    float* Wh = Ah + (SPLIT ? 2 : 1) * 32*132;
    float* Wl = SPLIT ? (Wh + 32*68) : Wh;

    const int t    = threadIdx.x;
    const int lane = t & 31;
    const int wid  = t >> 5;
    const int g    = lane >> 2;   // groupID
    const int q4   = lane & 3;    // threadID_in_group
    const int wm   = (wid >> 1) * 32;
    const int wn   = (wid & 1) * 32;
    const int m0   = blockIdx.y * 128;
    const int n0   = blockIdx.x * 64;

    float acc[2][4][4] = {};

    for (int k0 = 0; k0 < DM; k0 += 32) {
        // --- A tile 128x32 -> Ah/Al [k][m]
        #pragma unroll
        for (int i = 0; i < 4; i++) {
            int e  = t + i * 256;          // float4 id 0..1023
            int m  = e >> 3;
            int kq = e & 7;
            float4 a4 = *(const float4*)&A[(size_t)(m0 + m) * DM + k0 + kq * 4];
            float v[4] = {a4.x, a4.y, a4.z, a4.w};
            #pragma unroll
            for (int j = 0; j < 4; j++) {
                float hi = to_tf32(v[j]);
                Ah[(kq * 4 + j) * 132 + m] = hi;
                if (SPLIT) Al[(kq * 4 + j) * 132 + m] = to_tf32(v[j] - hi);
            }
        }
        // --- W tile 32x64 -> Wh/Wl [k][n]
        #pragma unroll
        for (int i = 0; i < 2; i++) {
            int e  = t + i * 256;          // float4 id 0..511
            int k  = e >> 4;
            int n4 = e & 15;
            float4 w4 = *(const float4*)&W[(size_t)(k0 + k) * DM + n0 + n4 * 4];
            float v[4] = {w4.x, w4.y, w4.z, w4.w};
            #pragma unroll
            for (int j = 0; j < 4; j++) {
                float hi = to_tf32(v[j]);
                Wh[k * 68 + n4 * 4 + j] = hi;
                if (SPLIT) Wl[k * 68 + n4 * 4 + j] = to_tf32(v[j] - hi);
            }
        }
        __syncthreads();

        #pragma unroll
        for (int ks = 0; ks < 32; ks += 8) {
            float ah[2][4], al[2][4];
            #pragma unroll
            for (int mt = 0; mt < 2; mt++) {
                int r = wm + mt * 16 + g;
                ah[mt][0] = Ah[(ks + q4) * 132 + r];
                ah[mt][1] = Ah[(ks + q4) * 132 + r + 8];
                ah[mt][2] = Ah[(ks + q4 + 4) * 132 + r];
                ah[mt][3] = Ah[(ks + q4 + 4) * 132 + r + 8];
                if (SPLIT) {
                    al[mt][0] = Al[(ks + q4) * 132 + r];
                    al[mt][1] = Al[(ks + q4) * 132 + r + 8];
                    al[mt][2] = Al[(ks + q4 + 4) * 132 + r];
                    al[mt][3] = Al[(ks + q4 + 4) * 132 + r + 8];
                }
            }
            #pragma unroll
            for (int nt = 0; nt < 4; nt++) {
                int c = wn + nt * 8 + g;
                float bh[2] = { Wh[(ks + q4) * 68 + c], Wh[(ks + q4 + 4) * 68 + c] };
                float bl[2];
                if (SPLIT) {
                    bl[0] = Wl[(ks + q4) * 68 + c];
                    bl[1] = Wl[(ks + q4 + 4) * 68 + c];
                }
                #pragma unroll
                for (int mt = 0; mt < 2; mt++) {
                    mma8(acc[mt][nt], ah[mt], bh);
                    if (SPLIT) {
                        mma8(acc[mt][nt], ah[mt], bl);
                        mma8(acc[mt][nt], al[mt], bh);
                    }
                }
            }
        }
        __syncthreads();
    }

    // Epilogue. c0:(g, q4*2) c1:(g, q4*2+1) c2:(g+8, q4*2) c3:(g+8, q4*2+1)
    #pragma unroll
    for (int mt = 0; mt < 2; mt++) {
        #pragma unroll
        for (int nt = 0; nt < 4; nt++) {
            int r0 = m0 + wm + mt * 16 + g;
            int c0 = n0 + wn + nt * 8 + q4 * 2;
            float bb0 = bias[c0], bb1 = bias[c0 + 1];
            #pragma unroll
            for (int rr = 0; rr < 2; rr++) {
                int row = r0 + rr * 8;
                float2 v = make_float2(acc[mt][nt][rr * 2] + bb0,
                                       acc[mt][nt][rr * 2 + 1] + bb1);
                if (HEAD_SPLIT) {
                    int b  = row >> 11;          // /2048
                    int s  = row & 2047;
                    int h  = c0 >> 6;
                    int dh = c0 & 63;
                    *(float2*)&out[(size_t)((b * NH + h) * S_ + s) * DH + dh] = v;
                } else {
                    *(float2*)&out[(size_t)row * DM + c0] = v;
                }
            }
        }
    }
}

// ---------------------------------------------------------------------------
// Flash attention with mma.sync tf32.
// CTA: 64 queries, 4 warps (warp = 16-query band), key tiles of 64, Dh=64.
// QK^T plain tf32 (softmax attenuates score error ~30x); PV uses 2-term
// split on BOTH P and V (straight-through error path).
// smem: Qs[64][68] (tf32), Kts[dh][key], Vh/Vl[key][dh], Ph/Pl[q][key]
// ---------------------------------------------------------------------------
#define FLASH_SMEM (6 * 64 * 68 * 4)   // 104448 bytes

__global__ __launch_bounds__(128) void flash_mma()
{
    extern __shared__ float sm[];
    float* Qs  = sm;
    float* Kts = Qs  + 64 * 68;
    float* Vh  = Kts + 64 * 68;
    float* Vl  = Vh  + 64 * 68;
    float* Ph  = Vl  + 64 * 68;
    float* Pl  = Ph  + 64 * 68;

    const int t    = threadIdx.x;
    const int lane = t & 31;
    const int wid  = t >> 5;
    const int g    = lane >> 2;
    const int q4   = lane & 3;
    const int q0   = blockIdx.x * 64;
    const int bh   = blockIdx.y;
    const int r    = wid * 16 + g;    // this thread's row (and r+8) in tile

    const float* __restrict__ Qb = g_Q + (size_t)bh * S_ * DH;
    const float* __restrict__ Kb = g_K + (size_t)bh * S_ * DH;
    const float* __restrict__ Vb = g_V + (size_t)bh * S_ * DH;

    // Load Q tile (tf32 hi only), layout [m][k]
    #pragma unroll
    for (int i = 0; i < 8; i++) {
        int e  = t + i * 128;          // float4 id 0..1023
        int m  = e >> 4;
        int dq = e & 15;
        float4 v = *(const float4*)&Qb[(size_t)(q0 + m) * DH + dq * 4];
        float4 h4 = make_float4(to_tf32(v.x), to_tf32(v.y), to_tf32(v.z), to_tf32(v.w));
        *(float4*)&Qs[m * 68 + dq * 4] = h4;
    }

    float o[8][4] = {};
    float mr0 = -1e30f, mr1 = -1e30f, lr0 = 0.0f, lr1 = 0.0f;
    __syncthreads();

    for (int kt = 0; kt < S_; kt += 64) {
        __syncthreads();   // protect K/V/P smem from overwrite while in use

        // Load K (transposed, tf32) and V (hi/lo split)
        #pragma unroll
        for (int i = 0; i < 8; i++) {
            int e  = t + i * 128;
            int m  = e >> 4;
            int dq = e & 15;
            int d  = dq * 4;
            float4 k4 = *(const float4*)&Kb[(size_t)(kt + m) * DH + d];
            Kts[(d + 0) * 68 + m] = to_tf32(k4.x);
            Kts[(d + 1) * 68 + m] = to_tf32(k4.y);
            Kts[(d + 2) * 68 + m] = to_tf32(k4.z);
            Kts[(d + 3) * 68 + m] = to_tf32(k4.w);
            float4 v4 = *(const float4*)&Vb[(size_t)(kt + m) * DH + d];
            float4 h4 = make_float4(to_tf32(v4.x), to_tf32(v4.y),
                                    to_tf32(v4.z), to_tf32(v4.w));
            float4 l4 = make_float4(to_tf32(v4.x - h4.x), to_tf32(v4.y - h4.y),
                                    to_tf32(v4.z - h4.z), to_tf32(v4.w - h4.w));
            *(float4*)&Vh[m * 68 + d] = h4;
            *(float4*)&Vl[m * 68 + d] = l4;
        }
        __syncthreads();

        // ---- QK^T: s = Q @ K^T  (plain tf32)
        float s[8][4] = {};
        #pragma unroll
        for (int ks = 0; ks < DH; ks += 8) {
            float a[4];
            a[0] = Qs[r * 68 + ks + q4];
            a[1] = Qs[(r + 8) * 68 + ks + q4];
            a[2] = Qs[r * 68 + ks + q4 + 4];
            a[3] = Qs[(r + 8) * 68 + ks + q4 + 4];
            #pragma unroll
            for (int nt = 0; nt < 8; nt++) {
                float b[2] = { Kts[(ks + q4) * 68 + nt * 8 + g],
                               Kts[(ks + q4 + 4) * 68 + nt * 8 + g] };
                mma8(s[nt], a, b);
            }
        }

        // ---- online softmax (rows r and r+8; quad lanes hold same rows)
        float rm0 = -1e30f, rm1 = -1e30f;
        #pragma unroll
        for (int nt = 0; nt < 8; nt++) {
            s[nt][0] *= SCALE; s[nt][1] *= SCALE;
            s[nt][2] *= SCALE; s[nt][3] *= SCALE;
            rm0 = fmaxf(rm0, fmaxf(s[nt][0], s[nt][1]));
            rm1 = fmaxf(rm1, fmaxf(s[nt][2], s[nt][3]));
        }
        rm0 = fmaxf(rm0, __shfl_xor_sync(0xffffffffu, rm0, 1));
        rm0 = fmaxf(rm0, __shfl_xor_sync(0xffffffffu, rm0, 2));
        rm1 = fmaxf(rm1, __shfl_xor_sync(0xffffffffu, rm1, 1));
        rm1 = fmaxf(rm1, __shfl_xor_sync(0xffffffffu, rm1, 2));
        float nm0 = fmaxf(mr0, rm0), nm1 = fmaxf(mr1, rm1);
        float cr0 = __expf(mr0 - nm0), cr1 = __expf(mr1 - nm1);
        float sum0 = 0.0f, sum1 = 0.0f;
        #pragma unroll
        for (int nt = 0; nt < 8; nt++) {
            s[nt][0] = __expf(s[nt][0] - nm0); sum0 += s[nt][0];
            s[nt][1] = __expf(s[nt][1] - nm0); sum0 += s[nt][1];
            s[nt][2] = __expf(s[nt][2] - nm1); sum1 += s[nt][2];
            s[nt][3] = __expf(s[nt][3] - nm1); sum1 += s[nt][3];
        }
        sum0 += __shfl_xor_sync(0xffffffffu, sum0, 1);
        sum0 += __shfl_xor_sync(0xffffffffu, sum0, 2);
        sum1 += __shfl_xor_sync(0xffffffffu, sum1, 1);
        sum1 += __shfl_xor_sync(0xffffffffu, sum1, 2);
        lr0 = lr0 * cr0 + sum0;  mr0 = nm0;
        lr1 = lr1 * cr1 + sum1;  mr1 = nm1;
        #pragma unroll
        for (int nt = 0; nt < 8; nt++) {
            o[nt][0] *= cr0; o[nt][1] *= cr0;
            o[nt][2] *= cr1; o[nt][3] *= cr1;
        }

        // ---- write P (hi/lo split), layout [q][key]; warp-local rows only
        #pragma unroll
        for (int nt = 0; nt < 8; nt++) {
            int col = nt * 8 + q4 * 2;
            float h00 = to_tf32(s[nt][0]), h01 = to_tf32(s[nt][1]);
            *(float2*)&Ph[r * 68 + col] = make_float2(h00, h01);
            *(float2*)&Pl[r * 68 + col] =
                make_float2(to_tf32(s[nt][0] - h00), to_tf32(s[nt][1] - h01));
            float h10 = to_tf32(s[nt][2]), h11 = to_tf32(s[nt][3]);
            *(float2*)&Ph[(r + 8) * 68 + col] = make_float2(h10, h11);
            *(float2*)&Pl[(r + 8) * 68 + col] =
                make_float2(to_tf32(s[nt][2] - h10), to_tf32(s[nt][3] - h11));
        }
        __syncwarp();   // P is read only by the warp that wrote it

        // ---- PV: o += P @ V  (split: Ph*Vh + Ph*Vl + Pl*Vh)
        #pragma unroll
        for (int ks = 0; ks < 64; ks += 8) {
            float ah[4], al[4];
            ah[0] = Ph[r * 68 + ks + q4];
            ah[1] = Ph[(r + 8) * 68 + ks + q4];
            ah[2] = Ph[r * 68 + ks + q4 + 4];
            ah[3] = Ph[(r + 8) * 68 + ks + q4 + 4];
            al[0] = Pl[r * 68 + ks + q4];
            al[1] = Pl[(r + 8) * 68 + ks + q4];
            al[2] = Pl[r * 68 + ks + q4 + 4];
            al[3] = Pl[(r + 8) * 68 + ks + q4 + 4];
            #pragma unroll
            for (int nt = 0; nt < 8; nt++) {
                float bh[2] = { Vh[(ks + q4) * 68 + nt * 8 + g],
                                Vh[(ks + q4 + 4) * 68 + nt * 8 + g] };
                float bl[2] = { Vl[(ks + q4) * 68 + nt * 8 + g],
                                Vl[(ks + q4 + 4) * 68 + nt * 8 + g] };
                mma8(o[nt], ah, bh);
                mma8(o[nt], ah, bl);
                mma8(o[nt], al, bh);
            }
        }
    }

    // Epilogue: normalize, write merged-head layout [b, s, h*64 + dh]
    const int b = bh >> 3;
    const int h = bh & 7;
    float inv0 = 1.0f / lr0, inv1 = 1.0f / lr1;
    #pragma unroll
    for (int nt = 0; nt < 8; nt++) {
        int col = h * DH + nt * 8 + q4 * 2;
        int qr0 = q0 + r;
        *(float2*)&g_att[(size_t)(b * S_ + qr0) * DM + col] =
            make_float2(o[nt][0] * inv0, o[nt][1] * inv0);
        int qr1 = q0 + r + 8;
        *(float2*)&g_att[(size_t)(b * S_ + qr1) * DM + col] =
            make_float2(o[nt][2] * inv1, o[nt][3] * inv1);
    }
}

// ---------------------------------------------------------------------------
extern "C" void kernel_launch(void* const* d_in, const int* in_sizes, int n_in,
                              void* d_out, int out_size)
{
    const float* x  = (const float*)d_in[0];
    const float* Wq = (const float*)d_in[1];
    const float* bq = (const float*)d_in[2];
    const float* Wk = (const float*)d_in[3];
    const float* bk = (const float*)d_in[4];
    const float* Wv = (const float*)d_in[5];
    const float* bv = (const float*)d_in[6];
    const float* Wo = (const float*)d_in[7];
    const float* bo = (const float*)d_in[8];
    float* out = (float*)d_out;

    void *pQ, *pK, *pV, *pA;
    cudaGetSymbolAddress(&pQ, g_Q);
    cudaGetSymbolAddress(&pK, g_K);
    cudaGetSymbolAddress(&pV, g_V);
    cudaGetSymbolAddress(&pA, g_att);

    cudaFuncSetAttribute(mma_gemm<false, true>,
                         cudaFuncAttributeMaxDynamicSharedMemorySize, GEMM_SMEM(false));
    cudaFuncSetAttribute(mma_gemm<true, true>,
                         cudaFuncAttributeMaxDynamicSharedMemorySize, GEMM_SMEM(true));
    cudaFuncSetAttribute(mma_gemm<true, false>,
                         cudaFuncAttributeMaxDynamicSharedMemorySize, GEMM_SMEM(true));
    cudaFuncSetAttribute(flash_mma,
                         cudaFuncAttributeMaxDynamicSharedMemorySize, FLASH_SMEM);

    dim3 ggrid(DM / 64, (B_ * S_) / 128);   // (8, 64)

    // Q/K projections: plain tf32 (score-path error attenuated by softmax)
    mma_gemm<false, true><<<ggrid, 256, GEMM_SMEM(false)>>>(x, Wq, bq, (float*)pQ);
    mma_gemm<false, true><<<ggrid, 256, GEMM_SMEM(false)>>>(x, Wk, bk, (float*)pK);
    // V projection: split (value-path error passes straight through)
    mma_gemm<true, true><<<ggrid, 256, GEMM_SMEM(true)>>>(x, Wv, bv, (float*)pV);

    flash_mma<<<dim3(S_ / 64, B_ * NH), 128, FLASH_SMEM>>>();

    // Output projection: split
    mma_gemm<true, false><<<ggrid, 256, GEMM_SMEM(true)>>>((const float*)pA, Wo, bo, out);
}

// round 13
// speedup vs baseline: 1.5603x; 1.1693x over previous
#include <cuda_runtime.h>
#include <math.h>
#include <stdint.h>

#define B_   4
#define S_   2048
#define DM   512
#define NH   8
#define DH   64
#define SCALE 0.044194173824159216f  // 1/sqrt(512)

// Scratch (device globals — no allocation allowed)
__device__ float g_Q[B_ * NH * S_ * DH];     // [b,h,s,dh]
__device__ float g_K[B_ * NH * S_ * DH];
__device__ float g_V[B_ * NH * S_ * DH];
__device__ float g_att[B_ * S_ * DM];        // [b,s,h*dh]

// ---------------------------------------------------------------------------
__device__ __forceinline__ float to_tf32(float x) {
    uint32_t u;
    asm("cvt.rna.tf32.f32 %0, %1;" : "=r"(u) : "f"(x));
    return __uint_as_float(u);
}

// D += A(16x8) * B(8x8), tf32 inputs, f32 accumulate.
__device__ __forceinline__ void mma8(float d[4], const float a[4], const float b[2]) {
    uint32_t const* A = reinterpret_cast<uint32_t const*>(a);
    uint32_t const* Bf = reinterpret_cast<uint32_t const*>(b);
    asm volatile(
        "mma.sync.aligned.m16n8k8.row.col.f32.tf32.tf32.f32 "
        "{%0,%1,%2,%3}, {%4,%5,%6,%7}, {%8,%9}, {%0,%1,%2,%3};"
        : "+f"(d[0]), "+f"(d[1]), "+f"(d[2]), "+f"(d[3])
        : "r"(A[0]), "r"(A[1]), "r"(A[2]), "r"(A[3]),
          "r"(Bf[0]), "r"(Bf[1]));
}

// ---------------------------------------------------------------------------
// GEMM via mma.sync: C[M,512] = A[M,512] @ W[512,512] + bias
// BM=128, BN=64, BK=32. 256 threads = 8 warps (4x2), warp tile 32x32.
// ---------------------------------------------------------------------------
#define GEMM_SMEM(SPLIT) ((SPLIT ? 2 : 1) * (32*132 + 32*68) * 4)

template <bool SPLIT, bool HEAD_SPLIT>
__global__ __launch_bounds__(256) void mma_gemm(
    const float* __restrict__ A,
    const float* __restrict__ W,
    const float* __restrict__ bias,
    float* __restrict__ out)
{
    extern __shared__ float sm[];
    float* Ah = sm;
    float* Al = SPLIT ? (Ah + 32*132) : Ah;
    float* Wh = Ah + (SPLIT ? 2 : 1) * 32*132;
    float* Wl = SPLIT ? (Wh + 32*68) : Wh;

    const int t    = threadIdx.x;
    const int lane = t & 31;
    const int wid  = t >> 5;
    const int g    = lane >> 2;
    const int q4   = lane & 3;
    const int wm   = (wid >> 1) * 32;
    const int wn   = (wid & 1) * 32;
    const int m0   = blockIdx.y * 128;
    const int n0   = blockIdx.x * 64;

    float acc[2][4][4] = {};

    for (int k0 = 0; k0 < DM; k0 += 32) {
        #pragma unroll
        for (int i = 0; i < 4; i++) {
            int e  = t + i * 256;
            int m  = e >> 3;
            int kq = e & 7;
            float4 a4 = *(const float4*)&A[(size_t)(m0 + m) * DM + k0 + kq * 4];
            float v[4] = {a4.x, a4.y, a4.z, a4.w};
            #pragma unroll
            for (int j = 0; j < 4; j++) {
                float hi = to_tf32(v[j]);
                Ah[(kq * 4 + j) * 132 + m] = hi;
                if (SPLIT) Al[(kq * 4 + j) * 132 + m] = to_tf32(v[j] - hi);
            }
        }
        #pragma unroll
        for (int i = 0; i < 2; i++) {
            int e  = t + i * 256;
            int k  = e >> 4;
            int n4 = e & 15;
            float4 w4 = *(const float4*)&W[(size_t)(k0 + k) * DM + n0 + n4 * 4];
            float v[4] = {w4.x, w4.y, w4.z, w4.w};
            #pragma unroll
            for (int j = 0; j < 4; j++) {
                float hi = to_tf32(v[j]);
                Wh[k * 68 + n4 * 4 + j] = hi;
                if (SPLIT) Wl[k * 68 + n4 * 4 + j] = to_tf32(v[j] - hi);
            }
        }
        __syncthreads();

        #pragma unroll
        for (int ks = 0; ks < 32; ks += 8) {
            float ah[2][4], al[2][4];
            #pragma unroll
            for (int mt = 0; mt < 2; mt++) {
                int r = wm + mt * 16 + g;
                ah[mt][0] = Ah[(ks + q4) * 132 + r];
                ah[mt][1] = Ah[(ks + q4) * 132 + r + 8];
                ah[mt][2] = Ah[(ks + q4 + 4) * 132 + r];
                ah[mt][3] = Ah[(ks + q4 + 4) * 132 + r + 8];
                if (SPLIT) {
                    al[mt][0] = Al[(ks + q4) * 132 + r];
                    al[mt][1] = Al[(ks + q4) * 132 + r + 8];
                    al[mt][2] = Al[(ks + q4 + 4) * 132 + r];
                    al[mt][3] = Al[(ks + q4 + 4) * 132 + r + 8];
                }
            }
            #pragma unroll
            for (int nt = 0; nt < 4; nt++) {
                int c = wn + nt * 8 + g;
                float bh[2] = { Wh[(ks + q4) * 68 + c], Wh[(ks + q4 + 4) * 68 + c] };
                float bl[2];
                if (SPLIT) {
                    bl[0] = Wl[(ks + q4) * 68 + c];
                    bl[1] = Wl[(ks + q4 + 4) * 68 + c];
                }
                #pragma unroll
                for (int mt = 0; mt < 2; mt++) {
                    mma8(acc[mt][nt], ah[mt], bh);
                    if (SPLIT) {
                        mma8(acc[mt][nt], ah[mt], bl);
                        mma8(acc[mt][nt], al[mt], bh);
                    }
                }
            }
        }
        __syncthreads();
    }

    #pragma unroll
    for (int mt = 0; mt < 2; mt++) {
        #pragma unroll
        for (int nt = 0; nt < 4; nt++) {
            int r0 = m0 + wm + mt * 16 + g;
            int c0 = n0 + wn + nt * 8 + q4 * 2;
            float bb0 = bias[c0], bb1 = bias[c0 + 1];
            #pragma unroll
            for (int rr = 0; rr < 2; rr++) {
                int row = r0 + rr * 8;
                float2 v = make_float2(acc[mt][nt][rr * 2] + bb0,
                                       acc[mt][nt][rr * 2 + 1] + bb1);
                if (HEAD_SPLIT) {
                    int b  = row >> 11;
                    int s  = row & 2047;
                    int h  = c0 >> 6;
                    int dh = c0 & 63;
                    *(float2*)&out[(size_t)((b * NH + h) * S_ + s) * DH + dh] = v;
                } else {
                    *(float2*)&out[(size_t)row * DM + c0] = v;
                }
            }
        }
    }
}

// ---------------------------------------------------------------------------
// Fused Q+K projection (plain tf32, shared A tile, two W/accumulator sets).
// ---------------------------------------------------------------------------
#define QK_SMEM ((32*132 + 2*32*68) * 4)

__global__ __launch_bounds__(256) void qk_gemm(
    const float* __restrict__ A,
    const float* __restrict__ Wq, const float* __restrict__ bq,
    const float* __restrict__ Wk, const float* __restrict__ bk,
    float* __restrict__ outQ, float* __restrict__ outK)
{
    extern __shared__ float sm[];
    float* Ah  = sm;
    float* Wqs = Ah  + 32*132;
    float* Wks = Wqs + 32*68;

    const int t    = threadIdx.x;
    const int lane = t & 31;
    const int wid  = t >> 5;
    const int g    = lane >> 2;
    const int q4   = lane & 3;
    const int wm   = (wid >> 1) * 32;
    const int wn   = (wid & 1) * 32;
    const int m0   = blockIdx.y * 128;
    const int n0   = blockIdx.x * 64;

    float aq[2][4][4] = {}, ak[2][4][4] = {};

    for (int k0 = 0; k0 < DM; k0 += 32) {
        #pragma unroll
        for (int i = 0; i < 4; i++) {
            int e  = t + i * 256;
            int m  = e >> 3;
            int kq = e & 7;
            float4 a4 = *(const float4*)&A[(size_t)(m0 + m) * DM + k0 + kq * 4];
            float v[4] = {a4.x, a4.y, a4.z, a4.w};
            #pragma unroll
            for (int j = 0; j < 4; j++)
                Ah[(kq * 4 + j) * 132 + m] = to_tf32(v[j]);
        }
        #pragma unroll
        for (int i = 0; i < 2; i++) {
            int e  = t + i * 256;
            int k  = e >> 4;
            int n4 = e & 15;
            size_t off = (size_t)(k0 + k) * DM + n0 + n4 * 4;
            float4 w4 = *(const float4*)&Wq[off];
            float4 w5 = *(const float4*)&Wk[off];
            float vq[4] = {w4.x, w4.y, w4.z, w4.w};
            float vk[4] = {w5.x, w5.y, w5.z, w5.w};
            #pragma unroll
            for (int j = 0; j < 4; j++) {
                Wqs[k * 68 + n4 * 4 + j] = to_tf32(vq[j]);
                Wks[k * 68 + n4 * 4 + j] = to_tf32(vk[j]);
            }
        }
        __syncthreads();

        #pragma unroll
        for (int ks = 0; ks < 32; ks += 8) {
            float a[2][4];
            #pragma unroll
            for (int mt = 0; mt < 2; mt++) {
                int r = wm + mt * 16 + g;
                a[mt][0] = Ah[(ks + q4) * 132 + r];
                a[mt][1] = Ah[(ks + q4) * 132 + r + 8];
                a[mt][2] = Ah[(ks + q4 + 4) * 132 + r];
                a[mt][3] = Ah[(ks + q4 + 4) * 132 + r + 8];
            }
            #pragma unroll
            for (int nt = 0; nt < 4; nt++) {
                int c = wn + nt * 8 + g;
                float bq2[2] = { Wqs[(ks + q4) * 68 + c], Wqs[(ks + q4 + 4) * 68 + c] };
                float bk2[2] = { Wks[(ks + q4) * 68 + c], Wks[(ks + q4 + 4) * 68 + c] };
                #pragma unroll
                for (int mt = 0; mt < 2; mt++) {
                    mma8(aq[mt][nt], a[mt], bq2);
                    mma8(ak[mt][nt], a[mt], bk2);
                }
            }
        }
        __syncthreads();
    }

    #pragma unroll
    for (int mt = 0; mt < 2; mt++) {
        #pragma unroll
        for (int nt = 0; nt < 4; nt++) {
            int r0 = m0 + wm + mt * 16 + g;
            int c0 = n0 + wn + nt * 8 + q4 * 2;
            float bbq0 = bq[c0], bbq1 = bq[c0 + 1];
            float bbk0 = bk[c0], bbk1 = bk[c0 + 1];
            int h  = c0 >> 6;
            int dh = c0 & 63;
            #pragma unroll
            for (int rr = 0; rr < 2; rr++) {
                int row = r0 + rr * 8;
                int b  = row >> 11;
                int s  = row & 2047;
                size_t o = (size_t)((b * NH + h) * S_ + s) * DH + dh;
                *(float2*)&outQ[o] = make_float2(aq[mt][nt][rr * 2] + bbq0,
                                                 aq[mt][nt][rr * 2 + 1] + bbq1);
                *(float2*)&outK[o] = make_float2(ak[mt][nt][rr * 2] + bbk0,
                                                 ak[mt][nt][rr * 2 + 1] + bbk1);
            }
        }
    }
}

// ---------------------------------------------------------------------------
// Flash attention, mma.sync tf32.
// CTA: 128 queries, 4 warps (128 threads). Warp = 32-query band (2 m-tiles).
// 64-key tiles. QK^T plain tf32 (Q pre-scaled by SCALE); PV 2-term split.
// P never touches smem: C-fragment -> A-fragment via 8 shfl + 4 selects per
// 16x8 block. smem: Qs[128][68], Ks[64][68], Vh/Vl[64][72] = 89,088 B
// (2 CTAs/SM). All smem reads bank-conflict-free by stride choice.
// ---------------------------------------------------------------------------
#define FLASH_SMEM ((128*68 + 64*68 + 2*64*72) * 4)   // 89088 bytes

__global__ __launch_bounds__(128) void flash_mma()
{
    extern __shared__ float sm[];
    float* Qs = sm;                  // [128][68]  q-major
    float* Ks = Qs + 128 * 68;       // [64][68]   key-major
    float* Vh = Ks + 64 * 68;        // [64][72]   key-major
    float* Vl = Vh + 64 * 72;

    const int t    = threadIdx.x;
    const int lane = t & 31;
    const int wid  = t >> 5;         // 0..3
    const int g    = lane >> 2;
    const int q4   = lane & 3;
    const int q0   = blockIdx.x * 128;
    const int bh   = blockIdx.y;

    const float* __restrict__ Qb = g_Q + (size_t)bh * S_ * DH;
    const float* __restrict__ Kb = g_K + (size_t)bh * S_ * DH;
    const float* __restrict__ Vb = g_V + (size_t)bh * S_ * DH;

    // Load Q tile (pre-scaled, tf32), [q][dh]: 2048 float4 over 128 threads
    #pragma unroll
    for (int i = 0; i < 16; i++) {
        int e  = t + i * 128;
        int m  = e >> 4;
        int dq = e & 15;
        float4 v = *(const float4*)&Qb[(size_t)(q0 + m) * DH + dq * 4];
        *(float4*)&Qs[m * 68 + dq * 4] =
            make_float4(to_tf32(v.x * SCALE), to_tf32(v.y * SCALE),
                        to_tf32(v.z * SCALE), to_tf32(v.w * SCALE));
    }

    float o[2][8][4] = {};
    float mr[2][2], lr[2][2];
    #pragma unroll
    for (int mt = 0; mt < 2; mt++) {
        mr[mt][0] = -1e30f; mr[mt][1] = -1e30f;
        lr[mt][0] = 0.0f;   lr[mt][1] = 0.0f;
    }
    __syncthreads();

    const int L1 = 4 * g + (q4 >> 1);   // shuffle source lane (and L1+2)
    const bool odd = (q4 & 1);

    for (int kt = 0; kt < S_; kt += 64) {
        __syncthreads();   // all warps done reading K/V of previous tile

        // Load K (tf32, [key][dh]) and V (hi/lo split): 1024 float4 / 128 thr
        #pragma unroll
        for (int i = 0; i < 8; i++) {
            int e  = t + i * 128;
            int m  = e >> 4;
            int dq = e & 15;
            int d  = dq * 4;
            float4 k4 = *(const float4*)&Kb[(size_t)(kt + m) * DH + d];
            *(float4*)&Ks[m * 68 + d] =
                make_float4(to_tf32(k4.x), to_tf32(k4.y), to_tf32(k4.z), to_tf32(k4.w));
            float4 v4 = *(const float4*)&Vb[(size_t)(kt + m) * DH + d];
            float4 h4 = make_float4(to_tf32(v4.x), to_tf32(v4.y),
                                    to_tf32(v4.z), to_tf32(v4.w));
            *(float4*)&Vh[m * 72 + d] = h4;
            *(float4*)&Vl[m * 72 + d] =
                make_float4(to_tf32(v4.x - h4.x), to_tf32(v4.y - h4.y),
                            to_tf32(v4.z - h4.z), to_tf32(v4.w - h4.w));
        }
        __syncthreads();

        #pragma unroll
        for (int mt = 0; mt < 2; mt++) {
            const int rb = wid * 32 + mt * 16;

            // ---- QK^T (Q pre-scaled)
            float s[8][4] = {};
            #pragma unroll
            for (int ks = 0; ks < DH; ks += 8) {
                float a[4];
                a[0] = Qs[(rb + g) * 68 + ks + q4];
                a[1] = Qs[(rb + g + 8) * 68 + ks + q4];
                a[2] = Qs[(rb + g) * 68 + ks + q4 + 4];
                a[3] = Qs[(rb + g + 8) * 68 + ks + q4 + 4];
                #pragma unroll
                for (int nt = 0; nt < 8; nt++) {
                    float b[2] = { Ks[(nt * 8 + g) * 68 + ks + q4],
                                   Ks[(nt * 8 + g) * 68 + ks + q4 + 4] };
                    mma8(s[nt], a, b);
                }
            }

            // ---- online softmax (rows rb+g and rb+g+8)
            float rm0 = -1e30f, rm1 = -1e30f;
            #pragma unroll
            for (int nt = 0; nt < 8; nt++) {
                rm0 = fmaxf(rm0, fmaxf(s[nt][0], s[nt][1]));
                rm1 = fmaxf(rm1, fmaxf(s[nt][2], s[nt][3]));
            }
            rm0 = fmaxf(rm0, __shfl_xor_sync(0xffffffffu, rm0, 1));
            rm0 = fmaxf(rm0, __shfl_xor_sync(0xffffffffu, rm0, 2));
            rm1 = fmaxf(rm1, __shfl_xor_sync(0xffffffffu, rm1, 1));
            rm1 = fmaxf(rm1, __shfl_xor_sync(0xffffffffu, rm1, 2));
            float nm0 = fmaxf(mr[mt][0], rm0), nm1 = fmaxf(mr[mt][1], rm1);
            float cr0 = __expf(mr[mt][0] - nm0), cr1 = __expf(mr[mt][1] - nm1);
            float sum0 = 0.0f, sum1 = 0.0f;
            #pragma unroll
            for (int nt = 0; nt < 8; nt++) {
                s[nt][0] = __expf(s[nt][0] - nm0); sum0 += s[nt][0];
                s[nt][1] = __expf(s[nt][1] - nm0); sum0 += s[nt][1];
                s[nt][2] = __expf(s[nt][2] - nm1); sum1 += s[nt][2];
                s[nt][3] = __expf(s[nt][3] - nm1); sum1 += s[nt][3];
            }
            sum0 += __shfl_xor_sync(0xffffffffu, sum0, 1);
            sum0 += __shfl_xor_sync(0xffffffffu, sum0, 2);
            sum1 += __shfl_xor_sync(0xffffffffu, sum1, 1);
            sum1 += __shfl_xor_sync(0xffffffffu, sum1, 2);
            lr[mt][0] = lr[mt][0] * cr0 + sum0;  mr[mt][0] = nm0;
            lr[mt][1] = lr[mt][1] * cr1 + sum1;  mr[mt][1] = nm1;
            #pragma unroll
            for (int nt = 0; nt < 8; nt++) {
                o[mt][nt][0] *= cr0; o[mt][nt][1] *= cr0;
                o[mt][nt][2] *= cr1; o[mt][nt][3] *= cr1;
            }

            // ---- PV: per 16x8 P-block, shuffle C-frag -> A-frag, split, mma
            #pragma unroll
            for (int kb = 0; kb < 8; kb++) {
                // C layout: lane(4g+q4') holds cols 2q4',2q4'+1 of rows g,g+8.
                // A layout needs cols q4 (a0,a1) and q4+4 (a2,a3).
                float x0 = __shfl_sync(0xffffffffu, s[kb][0], L1);
                float x1 = __shfl_sync(0xffffffffu, s[kb][1], L1);
                float x2 = __shfl_sync(0xffffffffu, s[kb][2], L1);
                float x3 = __shfl_sync(0xffffffffu, s[kb][3], L1);
                float y0 = __shfl_sync(0xffffffffu, s[kb][0], L1 + 2);
                float y1 = __shfl_sync(0xffffffffu, s[kb][1], L1 + 2);
                float y2 = __shfl_sync(0xffffffffu, s[kb][2], L1 + 2);
                float y3 = __shfl_sync(0xffffffffu, s[kb][3], L1 + 2);
                float a0 = odd ? x1 : x0;   // row g,   col q4
                float a1 = odd ? x3 : x2;   // row g+8, col q4
                float a2 = odd ? y1 : y0;   // row g,   col q4+4
                float a3 = odd ? y3 : y2;   // row g+8, col q4+4
                float ph[4] = { to_tf32(a0), to_tf32(a1), to_tf32(a2), to_tf32(a3) };
                float pl[4] = { to_tf32(a0 - ph[0]), to_tf32(a1 - ph[1]),
                                to_tf32(a2 - ph[2]), to_tf32(a3 - ph[3]) };
                #pragma unroll
                for (int nt = 0; nt < 8; nt++) {
                    float bh[2] = { Vh[(kb * 8 + q4) * 72 + nt * 8 + g],
                                    Vh[(kb * 8 + q4 + 4) * 72 + nt * 8 + g] };
                    float bl[2] = { Vl[(kb * 8 + q4) * 72 + nt * 8 + g],
                                    Vl[(kb * 8 + q4 + 4) * 72 + nt * 8 + g] };
                    mma8(o[mt][nt], ph, bh);
                    mma8(o[mt][nt], ph, bl);
                    mma8(o[mt][nt], pl, bh);
                }
            }
        }
    }

    // Epilogue: normalize, write merged-head layout [b, s, h*64 + dh]
    const int b = bh >> 3;
    const int h = bh & 7;
    #pragma unroll
    for (int mt = 0; mt < 2; mt++) {
        int rb = wid * 32 + mt * 16;
        float inv0 = 1.0f / lr[mt][0], inv1 = 1.0f / lr[mt][1];
        #pragma unroll
        for (int nt = 0; nt < 8; nt++) {
            int col = h * DH + nt * 8 + q4 * 2;
            int qr0 = q0 + rb + g;
            *(float2*)&g_att[(size_t)(b * S_ + qr0) * DM + col] =
                make_float2(o[mt][nt][0] * inv0, o[mt][nt][1] * inv0);
            int qr1 = q0 + rb + g + 8;
            *(float2*)&g_att[(size_t)(b * S_ + qr1) * DM + col] =
                make_float2(o[mt][nt][2] * inv1, o[mt][nt][3] * inv1);
        }
    }
}

// ---------------------------------------------------------------------------
extern "C" void kernel_launch(void* const* d_in, const int* in_sizes, int n_in,
                              void* d_out, int out_size)
{
    const float* x  = (const float*)d_in[0];
    const float* Wq = (const float*)d_in[1];
    const float* bq = (const float*)d_in[2];
    const float* Wk = (const float*)d_in[3];
    const float* bk = (const float*)d_in[4];
    const float* Wv = (const float*)d_in[5];
    const float* bv = (const float*)d_in[6];
    const float* Wo = (const float*)d_in[7];
    const float* bo = (const float*)d_in[8];
    float* out = (float*)d_out;

    void *pQ, *pK, *pV, *pA;
    cudaGetSymbolAddress(&pQ, g_Q);
    cudaGetSymbolAddress(&pK, g_K);
    cudaGetSymbolAddress(&pV, g_V);
    cudaGetSymbolAddress(&pA, g_att);

    cudaFuncSetAttribute(qk_gemm,
                         cudaFuncAttributeMaxDynamicSharedMemorySize, QK_SMEM);
    cudaFuncSetAttribute(mma_gemm<true, true>,
                         cudaFuncAttributeMaxDynamicSharedMemorySize, GEMM_SMEM(true));
    cudaFuncSetAttribute(mma_gemm<true, false>,
                         cudaFuncAttributeMaxDynamicSharedMemorySize, GEMM_SMEM(true));
    cudaFuncSetAttribute(flash_mma,
                         cudaFuncAttributeMaxDynamicSharedMemorySize, FLASH_SMEM);

    dim3 ggrid(DM / 64, (B_ * S_) / 128);   // (8, 64)

    // Q+K projections fused, plain tf32 (score-path error softmax-attenuated)
    qk_gemm<<<ggrid, 256, QK_SMEM>>>(x, Wq, bq, Wk, bk, (float*)pQ, (float*)pK);
    // V projection: split (value-path error passes straight through)
    mma_gemm<true, true><<<ggrid, 256, GEMM_SMEM(true)>>>(x, Wv, bv, (float*)pV);

    flash_mma<<<dim3(S_ / 128, B_ * NH), 128, FLASH_SMEM>>>();

    // Output projection: split
    mma_gemm<true, false><<<ggrid, 256, GEMM_SMEM(true)>>>((const float*)pA, Wo, bo, out);
}

// round 15
// speedup vs baseline: 2.1711x; 1.3914x over previous
#include <cuda_runtime.h>
#include <cuda_bf16.h>
#include <math.h>
#include <stdint.h>

#define B_   4
#define S_   2048
#define DM   512
#define NH   8
#define DH   64
#define SCALE 0.044194173824159216f  // 1/sqrt(512)

// Scratch (device globals — no allocation allowed)
__device__ float g_Q[B_ * NH * S_ * DH];     // [b,h,s,dh]
__device__ float g_K[B_ * NH * S_ * DH];
__device__ float g_V[B_ * NH * S_ * DH];
__device__ float g_att[B_ * S_ * DM];        // [b,s,h*dh]

// ---------------------------------------------------------------------------
__device__ __forceinline__ float to_tf32(float x) {
    uint32_t u;
    asm("cvt.rna.tf32.f32 %0, %1;" : "=r"(u) : "f"(x));
    return __uint_as_float(u);
}

// D += A(16x8) * B(8x8), tf32 inputs, f32 accumulate.
__device__ __forceinline__ void mma8(float d[4], const float a[4], const float b[2]) {
    uint32_t const* A = reinterpret_cast<uint32_t const*>(a);
    uint32_t const* Bf = reinterpret_cast<uint32_t const*>(b);
    asm volatile(
        "mma.sync.aligned.m16n8k8.row.col.f32.tf32.tf32.f32 "
        "{%0,%1,%2,%3}, {%4,%5,%6,%7}, {%8,%9}, {%0,%1,%2,%3};"
        : "+f"(d[0]), "+f"(d[1]), "+f"(d[2]), "+f"(d[3])
        : "r"(A[0]), "r"(A[1]), "r"(A[2]), "r"(A[3]),
          "r"(Bf[0]), "r"(Bf[1]));
}

// D += A(16x16) * B(16x8), bf16 inputs, f32 accumulate.
__device__ __forceinline__ void mma16(float d[4], const uint32_t a[4], const uint32_t b[2]) {
    asm volatile(
        "mma.sync.aligned.m16n8k16.row.col.f32.bf16.bf16.f32 "
        "{%0,%1,%2,%3}, {%4,%5,%6,%7}, {%8,%9}, {%0,%1,%2,%3};"
        : "+f"(d[0]), "+f"(d[1]), "+f"(d[2]), "+f"(d[3])
        : "r"(a[0]), "r"(a[1]), "r"(a[2]), "r"(a[3]),
          "r"(b[0]), "r"(b[1]));
}

__device__ __forceinline__ uint32_t packbf(float x, float y) {
    __nv_bfloat162 p = __floats2bfloat162_rn(x, y);
    return *reinterpret_cast<uint32_t*>(&p);
}
__device__ __forceinline__ float bfr(float x) {
    return __bfloat162float(__float2bfloat16_rn(x));
}

// ---------------------------------------------------------------------------
// GEMM via mma.sync: C[M,512] = A[M,512] @ W[512,512] + bias
// BM=128, BN=64, BK=32. 256 threads = 8 warps (4x2), warp tile 32x32.
// ---------------------------------------------------------------------------
#define GEMM_SMEM(SPLIT) ((SPLIT ? 2 : 1) * (32*132 + 32*68) * 4)

template <bool SPLIT, bool HEAD_SPLIT>
__global__ __launch_bounds__(256) void mma_gemm(
    const float* __restrict__ A,
    const float* __restrict__ W,
    const float* __restrict__ bias,
    float* __restrict__ out)
{
    extern __shared__ float sm[];
    float* Ah = sm;
    float* Al = SPLIT ? (Ah + 32*132) : Ah;
    float* Wh = Ah + (SPLIT ? 2 : 1) * 32*132;
    float* Wl = SPLIT ? (Wh + 32*68) : Wh;

    const int t    = threadIdx.x;
    const int lane = t & 31;
    const int wid  = t >> 5;
    const int g    = lane >> 2;
    const int q4   = lane & 3;
    const int wm   = (wid >> 1) * 32;
    const int wn   = (wid & 1) * 32;
    const int m0   = blockIdx.y * 128;
    const int n0   = blockIdx.x * 64;

    float acc[2][4][4] = {};

    for (int k0 = 0; k0 < DM; k0 += 32) {
        #pragma unroll
        for (int i = 0; i < 4; i++) {
            int e  = t + i * 256;
            int m  = e >> 3;
            int kq = e & 7;
            float4 a4 = *(const float4*)&A[(size_t)(m0 + m) * DM + k0 + kq * 4];
            float v[4] = {a4.x, a4.y, a4.z, a4.w};
            #pragma unroll
            for (int j = 0; j < 4; j++) {
                float hi = to_tf32(v[j]);
                Ah[(kq * 4 + j) * 132 + m] = hi;
                if (SPLIT) Al[(kq * 4 + j) * 132 + m] = to_tf32(v[j] - hi);
            }
        }
        #pragma unroll
        for (int i = 0; i < 2; i++) {
            int e  = t + i * 256;
            int k  = e >> 4;
            int n4 = e & 15;
            float4 w4 = *(const float4*)&W[(size_t)(k0 + k) * DM + n0 + n4 * 4];
            float v[4] = {w4.x, w4.y, w4.z, w4.w};
            #pragma unroll
            for (int j = 0; j < 4; j++) {
                float hi = to_tf32(v[j]);
                Wh[k * 68 + n4 * 4 + j] = hi;
                if (SPLIT) Wl[k * 68 + n4 * 4 + j] = to_tf32(v[j] - hi);
            }
        }
        __syncthreads();

        #pragma unroll
        for (int ks = 0; ks < 32; ks += 8) {
            float ah[2][4], al[2][4];
            #pragma unroll
            for (int mt = 0; mt < 2; mt++) {
                int r = wm + mt * 16 + g;
                ah[mt][0] = Ah[(ks + q4) * 132 + r];
                ah[mt][1] = Ah[(ks + q4) * 132 + r + 8];
                ah[mt][2] = Ah[(ks + q4 + 4) * 132 + r];
                ah[mt][3] = Ah[(ks + q4 + 4) * 132 + r + 8];
                if (SPLIT) {
                    al[mt][0] = Al[(ks + q4) * 132 + r];
                    al[mt][1] = Al[(ks + q4) * 132 + r + 8];
                    al[mt][2] = Al[(ks + q4 + 4) * 132 + r];
                    al[mt][3] = Al[(ks + q4 + 4) * 132 + r + 8];
                }
            }
            #pragma unroll
            for (int nt = 0; nt < 4; nt++) {
                int c = wn + nt * 8 + g;
                float bh[2] = { Wh[(ks + q4) * 68 + c], Wh[(ks + q4 + 4) * 68 + c] };
                float bl[2];
                if (SPLIT) {
                    bl[0] = Wl[(ks + q4) * 68 + c];
                    bl[1] = Wl[(ks + q4 + 4) * 68 + c];
                }
                #pragma unroll
                for (int mt = 0; mt < 2; mt++) {
                    mma8(acc[mt][nt], ah[mt], bh);
                    if (SPLIT) {
                        mma8(acc[mt][nt], ah[mt], bl);
                        mma8(acc[mt][nt], al[mt], bh);
                    }
                }
            }
        }
        __syncthreads();
    }

    #pragma unroll
    for (int mt = 0; mt < 2; mt++) {
        #pragma unroll
        for (int nt = 0; nt < 4; nt++) {
            int r0 = m0 + wm + mt * 16 + g;
            int c0 = n0 + wn + nt * 8 + q4 * 2;
            float bb0 = bias[c0], bb1 = bias[c0 + 1];
            #pragma unroll
            for (int rr = 0; rr < 2; rr++) {
                int row = r0 + rr * 8;
                float2 v = make_float2(acc[mt][nt][rr * 2] + bb0,
                                       acc[mt][nt][rr * 2 + 1] + bb1);
                if (HEAD_SPLIT) {
                    int b  = row >> 11;
                    int s  = row & 2047;
                    int h  = c0 >> 6;
                    int dh = c0 & 63;
                    *(float2*)&out[(size_t)((b * NH + h) * S_ + s) * DH + dh] = v;
                } else {
                    *(float2*)&out[(size_t)row * DM + c0] = v;
                }
            }
        }
    }
}

// ---------------------------------------------------------------------------
// Fused Q+K projection (plain tf32, shared A tile, two W/accumulator sets).
// ---------------------------------------------------------------------------
#define QK_SMEM ((32*132 + 2*32*68) * 4)

__global__ __launch_bounds__(256) void qk_gemm(
    const float* __restrict__ A,
    const float* __restrict__ Wq, const float* __restrict__ bq,
    const float* __restrict__ Wk, const float* __restrict__ bk,
    float* __restrict__ outQ, float* __restrict__ outK)
{
    extern __shared__ float sm[];
    float* Ah  = sm;
    float* Wqs = Ah  + 32*132;
    float* Wks = Wqs + 32*68;

    const int t    = threadIdx.x;
    const int lane = t & 31;
    const int wid  = t >> 5;
    const int g    = lane >> 2;
    const int q4   = lane & 3;
    const int wm   = (wid >> 1) * 32;
    const int wn   = (wid & 1) * 32;
    const int m0   = blockIdx.y * 128;
    const int n0   = blockIdx.x * 64;

    float aq[2][4][4] = {}, ak[2][4][4] = {};

    for (int k0 = 0; k0 < DM; k0 += 32) {
        #pragma unroll
        for (int i = 0; i < 4; i++) {
            int e  = t + i * 256;
            int m  = e >> 3;
            int kq = e & 7;
            float4 a4 = *(const float4*)&A[(size_t)(m0 + m) * DM + k0 + kq * 4];
            float v[4] = {a4.x, a4.y, a4.z, a4.w};
            #pragma unroll
            for (int j = 0; j < 4; j++)
                Ah[(kq * 4 + j) * 132 + m] = to_tf32(v[j]);
        }
        #pragma unroll
        for (int i = 0; i < 2; i++) {
            int e  = t + i * 256;
            int k  = e >> 4;
            int n4 = e & 15;
            size_t off = (size_t)(k0 + k) * DM + n0 + n4 * 4;
            float4 w4 = *(const float4*)&Wq[off];
            float4 w5 = *(const float4*)&Wk[off];
            float vq[4] = {w4.x, w4.y, w4.z, w4.w};
            float vk[4] = {w5.x, w5.y, w5.z, w5.w};
            #pragma unroll
            for (int j = 0; j < 4; j++) {
                Wqs[k * 68 + n4 * 4 + j] = to_tf32(vq[j]);
                Wks[k * 68 + n4 * 4 + j] = to_tf32(vk[j]);
            }
        }
        __syncthreads();

        #pragma unroll
        for (int ks = 0; ks < 32; ks += 8) {
            float a[2][4];
            #pragma unroll
            for (int mt = 0; mt < 2; mt++) {
                int r = wm + mt * 16 + g;
                a[mt][0] = Ah[(ks + q4) * 132 + r];
                a[mt][1] = Ah[(ks + q4) * 132 + r + 8];
                a[mt][2] = Ah[(ks + q4 + 4) * 132 + r];
                a[mt][3] = Ah[(ks + q4 + 4) * 132 + r + 8];
            }
            #pragma unroll
            for (int nt = 0; nt < 4; nt++) {
                int c = wn + nt * 8 + g;
                float bq2[2] = { Wqs[(ks + q4) * 68 + c], Wqs[(ks + q4 + 4) * 68 + c] };
                float bk2[2] = { Wks[(ks + q4) * 68 + c], Wks[(ks + q4 + 4) * 68 + c] };
                #pragma unroll
                for (int mt = 0; mt < 2; mt++) {
                    mma8(aq[mt][nt], a[mt], bq2);
                    mma8(ak[mt][nt], a[mt], bk2);
                }
            }
        }
        __syncthreads();
    }

    #pragma unroll
    for (int mt = 0; mt < 2; mt++) {
        #pragma unroll
        for (int nt = 0; nt < 4; nt++) {
            int r0 = m0 + wm + mt * 16 + g;
            int c0 = n0 + wn + nt * 8 + q4 * 2;
            float bbq0 = bq[c0], bbq1 = bq[c0 + 1];
            float bbk0 = bk[c0], bbk1 = bk[c0 + 1];
            int h  = c0 >> 6;
            int dh = c0 & 63;
            #pragma unroll
            for (int rr = 0; rr < 2; rr++) {
                int row = r0 + rr * 8;
                int b  = row >> 11;
                int s  = row & 2047;
                size_t o = (size_t)((b * NH + h) * S_ + s) * DH + dh;
                *(float2*)&outQ[o] = make_float2(aq[mt][nt][rr * 2] + bbq0,
                                                 aq[mt][nt][rr * 2 + 1] + bbq1);
                *(float2*)&outK[o] = make_float2(ak[mt][nt][rr * 2] + bbk0,
                                                 ak[mt][nt][rr * 2 + 1] + bbk1);
            }
        }
    }
}

// ---------------------------------------------------------------------------
// Flash attention. CTA: 128 queries, 4 warps (warp = 32-query band, 2 m-tiles),
// 64-key tiles. QK^T: plain tf32 (Q pre-scaled). PV: bf16 2-term split via
// mma.m16n8k16 — the tf32 QK C-fragment (cols 2q4,2q4+1) IS the bf16 A-frag
// layout, so P packs directly from registers (no shuffle, no smem).
// V stored key-pair-major Vt32[kp=32][72] u32 (bf16x2 along key):
//   fragment read bank = 8*q4 + g  -> conflict-free.
// smem: Qs[128][68] f32, Ks[64][68] f32, Vh32/Vl32 [32][72] u32 = 70656 B.
// ---------------------------------------------------------------------------
#define FLASH_SMEM ((128*68 + 64*68 + 2*32*72) * 4)   // 70656 bytes

__global__ __launch_bounds__(128) void flash_mma()
{
    extern __shared__ float sm[];
    float*    Qs   = sm;                       // [128][68]  q-major (tf32)
    float*    Ks   = Qs + 128 * 68;            // [64][68]   key-major (tf32)
    uint32_t* Vh32 = (uint32_t*)(Ks + 64 * 68);   // [32][72] bf16x2 (key pairs)
    uint32_t* Vl32 = Vh32 + 32 * 72;

    const int t    = threadIdx.x;
    const int lane = t & 31;
    const int wid  = t >> 5;         // 0..3
    const int g    = lane >> 2;
    const int q4   = lane & 3;
    const int q0   = blockIdx.x * 128;
    const int bh   = blockIdx.y;

    const float* __restrict__ Qb = g_Q + (size_t)bh * S_ * DH;
    const float* __restrict__ Kb = g_K + (size_t)bh * S_ * DH;
    const float* __restrict__ Vb = g_V + (size_t)bh * S_ * DH;

    // Load Q tile (pre-scaled, tf32), [q][dh]
    #pragma unroll
    for (int i = 0; i < 16; i++) {
        int e  = t + i * 128;
        int m  = e >> 4;
        int dq = e & 15;
        float4 v = *(const float4*)&Qb[(size_t)(q0 + m) * DH + dq * 4];
        *(float4*)&Qs[m * 68 + dq * 4] =
            make_float4(to_tf32(v.x * SCALE), to_tf32(v.y * SCALE),
                        to_tf32(v.z * SCALE), to_tf32(v.w * SCALE));
    }

    float o[2][8][4] = {};
    float mr[2][2], lr[2][2];
    #pragma unroll
    for (int mt = 0; mt < 2; mt++) {
        mr[mt][0] = -1e30f; mr[mt][1] = -1e30f;
        lr[mt][0] = 0.0f;   lr[mt][1] = 0.0f;
    }
    __syncthreads();

    const bool hihalf = (lane >= 16);   // holds odd key in V load pairing

    for (int kt = 0; kt < S_; kt += 64) {
        __syncthreads();   // all warps done reading K/V of previous tile

        // Load K (tf32, [key][dh]); V -> bf16 hi/lo, packed pairs along key.
        // Lanes l and l^16 hold keys m (even) and m+1 for the same dq.
        #pragma unroll
        for (int i = 0; i < 8; i++) {
            int e  = t + i * 128;
            int m  = e >> 4;
            int dq = e & 15;
            int d  = dq * 4;
            float4 k4 = *(const float4*)&Kb[(size_t)(kt + m) * DH + d];
            *(float4*)&Ks[m * 68 + d] =
                make_float4(to_tf32(k4.x), to_tf32(k4.y), to_tf32(k4.z), to_tf32(k4.w));

            float4 v4 = *(const float4*)&Vb[(size_t)(kt + m) * DH + d];
            float hv[4], lv[4];
            hv[0] = bfr(v4.x); lv[0] = v4.x - hv[0];
            hv[1] = bfr(v4.y); lv[1] = v4.y - hv[1];
            hv[2] = bfr(v4.z); lv[2] = v4.z - hv[2];
            hv[3] = bfr(v4.w); lv[3] = v4.w - hv[3];
            uint32_t hp[4], lp[4];
            #pragma unroll
            for (int j = 0; j < 4; j++) {
                float oh = __shfl_xor_sync(0xffffffffu, hv[j], 16);
                float ol = __shfl_xor_sync(0xffffffffu, lv[j], 16);
                hp[j] = hihalf ? packbf(oh, hv[j]) : packbf(hv[j], oh);
                lp[j] = hihalf ? packbf(ol, lv[j]) : packbf(lv[j], ol);
            }
            int kp = m >> 1;
            int jb = hihalf ? 2 : 0;
            Vh32[kp * 72 + d + jb]     = hp[jb];
            Vh32[kp * 72 + d + jb + 1] = hp[jb + 1];
            Vl32[kp * 72 + d + jb]     = lp[jb];
            Vl32[kp * 72 + d + jb + 1] = lp[jb + 1];
        }
        __syncthreads();

        #pragma unroll
        for (int mt = 0; mt < 2; mt++) {
            const int rb = wid * 32 + mt * 16;

            // ---- QK^T (Q pre-scaled, plain tf32)
            float s[8][4] = {};
            #pragma unroll
            for (int ks = 0; ks < DH; ks += 8) {
                float a[4];
                a[0] = Qs[(rb + g) * 68 + ks + q4];
                a[1] = Qs[(rb + g + 8) * 68 + ks + q4];
                a[2] = Qs[(rb + g) * 68 + ks + q4 + 4];
                a[3] = Qs[(rb + g + 8) * 68 + ks + q4 + 4];
                #pragma unroll
                for (int nt = 0; nt < 8; nt++) {
                    float b[2] = { Ks[(nt * 8 + g) * 68 + ks + q4],
                                   Ks[(nt * 8 + g) * 68 + ks + q4 + 4] };
                    mma8(s[nt], a, b);
                }
            }

            // ---- online softmax (rows rb+g and rb+g+8)
            float rm0 = -1e30f, rm1 = -1e30f;
            #pragma unroll
            for (int nt = 0; nt < 8; nt++) {
                rm0 = fmaxf(rm0, fmaxf(s[nt][0], s[nt][1]));
                rm1 = fmaxf(rm1, fmaxf(s[nt][2], s[nt][3]));
            }
            rm0 = fmaxf(rm0, __shfl_xor_sync(0xffffffffu, rm0, 1));
            rm0 = fmaxf(rm0, __shfl_xor_sync(0xffffffffu, rm0, 2));
            rm1 = fmaxf(rm1, __shfl_xor_sync(0xffffffffu, rm1, 1));
            rm1 = fmaxf(rm1, __shfl_xor_sync(0xffffffffu, rm1, 2));
            float nm0 = fmaxf(mr[mt][0], rm0), nm1 = fmaxf(mr[mt][1], rm1);
            float cr0 = __expf(mr[mt][0] - nm0), cr1 = __expf(mr[mt][1] - nm1);
            float sum0 = 0.0f, sum1 = 0.0f;
            #pragma unroll
            for (int nt = 0; nt < 8; nt++) {
                s[nt][0] = __expf(s[nt][0] - nm0); sum0 += s[nt][0];
                s[nt][1] = __expf(s[nt][1] - nm0); sum0 += s[nt][1];
                s[nt][2] = __expf(s[nt][2] - nm1); sum1 += s[nt][2];
                s[nt][3] = __expf(s[nt][3] - nm1); sum1 += s[nt][3];
            }
            sum0 += __shfl_xor_sync(0xffffffffu, sum0, 1);
            sum0 += __shfl_xor_sync(0xffffffffu, sum0, 2);
            sum1 += __shfl_xor_sync(0xffffffffu, sum1, 1);
            sum1 += __shfl_xor_sync(0xffffffffu, sum1, 2);
            lr[mt][0] = lr[mt][0] * cr0 + sum0;  mr[mt][0] = nm0;
            lr[mt][1] = lr[mt][1] * cr1 + sum1;  mr[mt][1] = nm1;
            #pragma unroll
            for (int nt = 0; nt < 8; nt++) {
                o[mt][nt][0] *= cr0; o[mt][nt][1] *= cr0;
                o[mt][nt][2] *= cr1; o[mt][nt][3] *= cr1;
            }

            // ---- PV: bf16 split, k16 slabs (keys 16ts..16ts+15).
            // A-frag packs directly from C-frag layout: no shuffle.
            #pragma unroll
            for (int ts = 0; ts < 4; ts++) {
                float p00 = s[2*ts][0],   p01 = s[2*ts][1];
                float p10 = s[2*ts][2],   p11 = s[2*ts][3];
                float p20 = s[2*ts+1][0], p21 = s[2*ts+1][1];
                float p30 = s[2*ts+1][2], p31 = s[2*ts+1][3];
                float h00 = bfr(p00), h01 = bfr(p01);
                float h10 = bfr(p10), h11 = bfr(p11);
                float h20 = bfr(p20), h21 = bfr(p21);
                float h30 = bfr(p30), h31 = bfr(p31);
                uint32_t ph[4] = { packbf(h00, h01), packbf(h10, h11),
                                   packbf(h20, h21), packbf(h30, h31) };
                uint32_t pl[4] = { packbf(p00 - h00, p01 - h01),
                                   packbf(p10 - h10, p11 - h11),
                                   packbf(p20 - h20, p21 - h21),
                                   packbf(p30 - h30, p31 - h31) };
                const uint32_t* vhr0 = Vh32 + (ts * 8 + q4) * 72;
                const uint32_t* vhr1 = Vh32 + (ts * 8 + 4 + q4) * 72;
                const uint32_t* vlr0 = Vl32 + (ts * 8 + q4) * 72;
                const uint32_t* vlr1 = Vl32 + (ts * 8 + 4 + q4) * 72;
                #pragma unroll
                for (int nt = 0; nt < 8; nt++) {
                    int c = nt * 8 + g;
                    uint32_t bh[2] = { vhr0[c], vhr1[c] };
                    uint32_t bl[2] = { vlr0[c], vlr1[c] };
                    mma16(o[mt][nt], ph, bh);
                    mma16(o[mt][nt], ph, bl);
                    mma16(o[mt][nt], pl, bh);
                }
            }
        }
    }

    // Epilogue: normalize, write merged-head layout [b, s, h*64 + dh]
    const int b = bh >> 3;
    const int h = bh & 7;
    #pragma unroll
    for (int mt = 0; mt < 2; mt++) {
        int rb = wid * 32 + mt * 16;
        float inv0 = 1.0f / lr[mt][0], inv1 = 1.0f / lr[mt][1];
        #pragma unroll
        for (int nt = 0; nt < 8; nt++) {
            int col = h * DH + nt * 8 + q4 * 2;
            int qr0 = q0 + rb + g;
            *(float2*)&g_att[(size_t)(b * S_ + qr0) * DM + col] =
                make_float2(o[mt][nt][0] * inv0, o[mt][nt][1] * inv0);
            int qr1 = q0 + rb + g + 8;
            *(float2*)&g_att[(size_t)(b * S_ + qr1) * DM + col] =
                make_float2(o[mt][nt][2] * inv1, o[mt][nt][3] * inv1);
        }
    }
}

// ---------------------------------------------------------------------------
extern "C" void kernel_launch(void* const* d_in, const int* in_sizes, int n_in,
                              void* d_out, int out_size)
{
    const float* x  = (const float*)d_in[0];
    const float* Wq = (const float*)d_in[1];
    const float* bq = (const float*)d_in[2];
    const float* Wk = (const float*)d_in[3];
    const float* bk = (const float*)d_in[4];
    const float* Wv = (const float*)d_in[5];
    const float* bv = (const float*)d_in[6];
    const float* Wo = (const float*)d_in[7];
    const float* bo = (const float*)d_in[8];
    float* out = (float*)d_out;

    void *pQ, *pK, *pV, *pA;
    cudaGetSymbolAddress(&pQ, g_Q);
    cudaGetSymbolAddress(&pK, g_K);
    cudaGetSymbolAddress(&pV, g_V);
    cudaGetSymbolAddress(&pA, g_att);

    cudaFuncSetAttribute(qk_gemm,
                         cudaFuncAttributeMaxDynamicSharedMemorySize, QK_SMEM);
    cudaFuncSetAttribute(mma_gemm<true, true>,
                         cudaFuncAttributeMaxDynamicSharedMemorySize, GEMM_SMEM(true));
    cudaFuncSetAttribute(mma_gemm<true, false>,
                         cudaFuncAttributeMaxDynamicSharedMemorySize, GEMM_SMEM(true));
    cudaFuncSetAttribute(flash_mma,
                         cudaFuncAttributeMaxDynamicSharedMemorySize, FLASH_SMEM);

    dim3 ggrid(DM / 64, (B_ * S_) / 128);   // (8, 64)

    // Q+K projections fused, plain tf32 (score-path error softmax-attenuated)
    qk_gemm<<<ggrid, 256, QK_SMEM>>>(x, Wq, bq, Wk, bk, (float*)pQ, (float*)pK);
    // V projection: split (value-path error passes straight through)
    mma_gemm<true, true><<<ggrid, 256, GEMM_SMEM(true)>>>(x, Wv, bv, (float*)pV);

    flash_mma<<<dim3(S_ / 128, B_ * NH), 128, FLASH_SMEM>>>();

    // Output projection: split
    mma_gemm<true, false><<<ggrid, 256, GEMM_SMEM(true)>>>((const float*)pA, Wo, bo, out);
}

// round 17
// speedup vs baseline: 2.5792x; 1.1880x over previous
#include <cuda_runtime.h>
#include <cuda_bf16.h>
#include <math.h>
#include <stdint.h>

#define B_   4
#define S_   2048
#define DM   512
#define NH   8
#define DH   64
#define SCALE 0.044194173824159216f  // 1/sqrt(512)

// Scratch (device globals — no allocation allowed)
__device__ float g_Q[B_ * NH * S_ * DH];     // [b,h,s,dh]
__device__ float g_K[B_ * NH * S_ * DH];
__device__ float g_V[B_ * NH * S_ * DH];
__device__ float g_att[B_ * S_ * DM];        // [b,s,h*dh]

// ---------------------------------------------------------------------------
__device__ __forceinline__ float to_tf32(float x) {
    uint32_t u;
    asm("cvt.rna.tf32.f32 %0, %1;" : "=r"(u) : "f"(x));
    return __uint_as_float(u);
}

// D += A(16x8) * B(8x8), tf32 inputs, f32 accumulate.
__device__ __forceinline__ void mma8(float d[4], const float a[4], const float b[2]) {
    uint32_t const* A = reinterpret_cast<uint32_t const*>(a);
    uint32_t const* Bf = reinterpret_cast<uint32_t const*>(b);
    asm volatile(
        "mma.sync.aligned.m16n8k8.row.col.f32.tf32.tf32.f32 "
        "{%0,%1,%2,%3}, {%4,%5,%6,%7}, {%8,%9}, {%0,%1,%2,%3};"
        : "+f"(d[0]), "+f"(d[1]), "+f"(d[2]), "+f"(d[3])
        : "r"(A[0]), "r"(A[1]), "r"(A[2]), "r"(A[3]),
          "r"(Bf[0]), "r"(Bf[1]));
}

// D += A(16x16) * B(16x8), bf16 inputs, f32 accumulate.
__device__ __forceinline__ void mma16(float d[4], const uint32_t a[4], const uint32_t b[2]) {
    asm volatile(
        "mma.sync.aligned.m16n8k16.row.col.f32.bf16.bf16.f32 "
        "{%0,%1,%2,%3}, {%4,%5,%6,%7}, {%8,%9}, {%0,%1,%2,%3};"
        : "+f"(d[0]), "+f"(d[1]), "+f"(d[2]), "+f"(d[3])
        : "r"(a[0]), "r"(a[1]), "r"(a[2]), "r"(a[3]),
          "r"(b[0]), "r"(b[1]));
}

__device__ __forceinline__ uint32_t packbf(float x, float y) {
    __nv_bfloat162 p = __floats2bfloat162_rn(x, y);
    return *reinterpret_cast<uint32_t*>(&p);
}
__device__ __forceinline__ float bfr(float x) {
    return __bfloat162float(__float2bfloat16_rn(x));
}

// ---------------------------------------------------------------------------
// bf16 2-term-split GEMM: C[M,512] = A[M,512] @ W[512,512] + bias.
// BM=128, BN=64, BK=32. 256 threads = 8 warps (4x2), warp tile 32x32.
// A/W stored as packed bf16x2 (hi and lo planes). Per k16 slab:
// 3 mma16 (AhBh + AhBl + AlBh). Conflict-free strides: Ap stride 20
// (bank = perm4(g)+q4), Wp stride 72 (bank = 8q4+g).
// ---------------------------------------------------------------------------
#define BF_SMEM ((2*128*20 + 2*16*72) * 4)   // 29696 bytes (u32 planes)

template <bool HEAD_SPLIT>
__global__ __launch_bounds__(256) void bf_gemm(
    const float* __restrict__ A,
    const float* __restrict__ W,
    const float* __restrict__ bias,
    float* __restrict__ out)
{
    extern __shared__ uint32_t smu[];
    uint32_t* Aph = smu;               // [128][20]
    uint32_t* Apl = Aph + 128 * 20;
    uint32_t* Wph = Apl + 128 * 20;    // [16][72]
    uint32_t* Wpl = Wph + 16 * 72;

    const int t    = threadIdx.x;
    const int lane = t & 31;
    const int wid  = t >> 5;
    const int g    = lane >> 2;
    const int q4   = lane & 3;
    const int wm   = (wid >> 1) * 32;
    const int wn   = (wid & 1) * 32;
    const int m0   = blockIdx.y * 128;
    const int n0   = blockIdx.x * 64;

    float acc[2][4][4] = {};

    for (int k0 = 0; k0 < DM; k0 += 32) {
        // --- A tile 128x32 -> packed bf16x2 hi/lo, [m][kp] stride 20
        #pragma unroll
        for (int i = 0; i < 4; i++) {
            int e  = t + i * 256;
            int m  = e >> 3;
            int kq = e & 7;
            float4 a4 = *(const float4*)&A[(size_t)(m0 + m) * DM + k0 + kq * 4];
            float h0 = bfr(a4.x), h1 = bfr(a4.y), h2 = bfr(a4.z), h3 = bfr(a4.w);
            Aph[m * 20 + kq * 2]     = packbf(h0, h1);
            Aph[m * 20 + kq * 2 + 1] = packbf(h2, h3);
            Apl[m * 20 + kq * 2]     = packbf(a4.x - h0, a4.y - h1);
            Apl[m * 20 + kq * 2 + 1] = packbf(a4.z - h2, a4.w - h3);
        }
        // --- W tile 32x64 -> packed pairs along k, [kp][n] stride 72
        {
            int kp = t >> 4;          // 0..15
            int nq = t & 15;          // 0..15
            const float* w0 = &W[(size_t)(k0 + kp * 2) * DM + n0 + nq * 4];
            float4 wa = *(const float4*)w0;
            float4 wb = *(const float4*)(w0 + DM);
            float ha0 = bfr(wa.x), ha1 = bfr(wa.y), ha2 = bfr(wa.z), ha3 = bfr(wa.w);
            float hb0 = bfr(wb.x), hb1 = bfr(wb.y), hb2 = bfr(wb.z), hb3 = bfr(wb.w);
            uint4 h = make_uint4(packbf(ha0, hb0), packbf(ha1, hb1),
                                 packbf(ha2, hb2), packbf(ha3, hb3));
            uint4 l = make_uint4(packbf(wa.x - ha0, wb.x - hb0),
                                 packbf(wa.y - ha1, wb.y - hb1),
                                 packbf(wa.z - ha2, wb.z - hb2),
                                 packbf(wa.w - ha3, wb.w - hb3));
            *(uint4*)&Wph[kp * 72 + nq * 4] = h;
            *(uint4*)&Wpl[kp * 72 + nq * 4] = l;
        }
        __syncthreads();

        #pragma unroll
        for (int slab = 0; slab < 2; slab++) {
            const int kb = slab * 8;
            uint32_t ah[2][4], al[2][4];
            #pragma unroll
            for (int mt = 0; mt < 2; mt++) {
                int r = wm + mt * 16 + g;
                ah[mt][0] = Aph[r * 20 + kb + q4];
                ah[mt][1] = Aph[(r + 8) * 20 + kb + q4];
                ah[mt][2] = Aph[r * 20 + kb + q4 + 4];
                ah[mt][3] = Aph[(r + 8) * 20 + kb + q4 + 4];
                al[mt][0] = Apl[r * 20 + kb + q4];
                al[mt][1] = Apl[(r + 8) * 20 + kb + q4];
                al[mt][2] = Apl[r * 20 + kb + q4 + 4];
                al[mt][3] = Apl[(r + 8) * 20 + kb + q4 + 4];
            }
            #pragma unroll
            for (int nt = 0; nt < 4; nt++) {
                int c = wn + nt * 8 + g;
                uint32_t bh[2] = { Wph[(kb + q4) * 72 + c], Wph[(kb + q4 + 4) * 72 + c] };
                uint32_t bl[2] = { Wpl[(kb + q4) * 72 + c], Wpl[(kb + q4 + 4) * 72 + c] };
                #pragma unroll
                for (int mt = 0; mt < 2; mt++) {
                    mma16(acc[mt][nt], ah[mt], bh);
                    mma16(acc[mt][nt], ah[mt], bl);
                    mma16(acc[mt][nt], al[mt], bh);
                }
            }
        }
        __syncthreads();
    }

    #pragma unroll
    for (int mt = 0; mt < 2; mt++) {
        #pragma unroll
        for (int nt = 0; nt < 4; nt++) {
            int r0 = m0 + wm + mt * 16 + g;
            int c0 = n0 + wn + nt * 8 + q4 * 2;
            float bb0 = bias[c0], bb1 = bias[c0 + 1];
            #pragma unroll
            for (int rr = 0; rr < 2; rr++) {
                int row = r0 + rr * 8;
                float2 v = make_float2(acc[mt][nt][rr * 2] + bb0,
                                       acc[mt][nt][rr * 2 + 1] + bb1);
                if (HEAD_SPLIT) {
                    int b  = row >> 11;
                    int s  = row & 2047;
                    int h  = c0 >> 6;
                    int dh = c0 & 63;
                    *(float2*)&out[(size_t)((b * NH + h) * S_ + s) * DH + dh] = v;
                } else {
                    *(float2*)&out[(size_t)row * DM + c0] = v;
                }
            }
        }
    }
}

// ---------------------------------------------------------------------------
// Fused Q+K projection (plain tf32, shared A tile, two W/accumulator sets).
// ---------------------------------------------------------------------------
#define QK_SMEM ((32*132 + 2*32*68) * 4)

__global__ __launch_bounds__(256) void qk_gemm(
    const float* __restrict__ A,
    const float* __restrict__ Wq, const float* __restrict__ bq,
    const float* __restrict__ Wk, const float* __restrict__ bk,
    float* __restrict__ outQ, float* __restrict__ outK)
{
    extern __shared__ float sm[];
    float* Ah  = sm;
    float* Wqs = Ah  + 32*132;
    float* Wks = Wqs + 32*68;

    const int t    = threadIdx.x;
    const int lane = t & 31;
    const int wid  = t >> 5;
    const int g    = lane >> 2;
    const int q4   = lane & 3;
    const int wm   = (wid >> 1) * 32;
    const int wn   = (wid & 1) * 32;
    const int m0   = blockIdx.y * 128;
    const int n0   = blockIdx.x * 64;

    float aq[2][4][4] = {}, ak[2][4][4] = {};

    for (int k0 = 0; k0 < DM; k0 += 32) {
        #pragma unroll
        for (int i = 0; i < 4; i++) {
            int e  = t + i * 256;
            int m  = e >> 3;
            int kq = e & 7;
            float4 a4 = *(const float4*)&A[(size_t)(m0 + m) * DM + k0 + kq * 4];
            float v[4] = {a4.x, a4.y, a4.z, a4.w};
            #pragma unroll
            for (int j = 0; j < 4; j++)
                Ah[(kq * 4 + j) * 132 + m] = to_tf32(v[j]);
        }
        #pragma unroll
        for (int i = 0; i < 2; i++) {
            int e  = t + i * 256;
            int k  = e >> 4;
            int n4 = e & 15;
            size_t off = (size_t)(k0 + k) * DM + n0 + n4 * 4;
            float4 w4 = *(const float4*)&Wq[off];
            float4 w5 = *(const float4*)&Wk[off];
            float vq[4] = {w4.x, w4.y, w4.z, w4.w};
            float vk[4] = {w5.x, w5.y, w5.z, w5.w};
            #pragma unroll
            for (int j = 0; j < 4; j++) {
                Wqs[k * 68 + n4 * 4 + j] = to_tf32(vq[j]);
                Wks[k * 68 + n4 * 4 + j] = to_tf32(vk[j]);
            }
        }
        __syncthreads();

        #pragma unroll
        for (int ks = 0; ks < 32; ks += 8) {
            float a[2][4];
            #pragma unroll
            for (int mt = 0; mt < 2; mt++) {
                int r = wm + mt * 16 + g;
                a[mt][0] = Ah[(ks + q4) * 132 + r];
                a[mt][1] = Ah[(ks + q4) * 132 + r + 8];
                a[mt][2] = Ah[(ks + q4 + 4) * 132 + r];
                a[mt][3] = Ah[(ks + q4 + 4) * 132 + r + 8];
            }
            #pragma unroll
            for (int nt = 0; nt < 4; nt++) {
                int c = wn + nt * 8 + g;
                float bq2[2] = { Wqs[(ks + q4) * 68 + c], Wqs[(ks + q4 + 4) * 68 + c] };
                float bk2[2] = { Wks[(ks + q4) * 68 + c], Wks[(ks + q4 + 4) * 68 + c] };
                #pragma unroll
                for (int mt = 0; mt < 2; mt++) {
                    mma8(aq[mt][nt], a[mt], bq2);
                    mma8(ak[mt][nt], a[mt], bk2);
                }
            }
        }
        __syncthreads();
    }

    #pragma unroll
    for (int mt = 0; mt < 2; mt++) {
        #pragma unroll
        for (int nt = 0; nt < 4; nt++) {
            int r0 = m0 + wm + mt * 16 + g;
            int c0 = n0 + wn + nt * 8 + q4 * 2;
            float bbq0 = bq[c0], bbq1 = bq[c0 + 1];
            float bbk0 = bk[c0], bbk1 = bk[c0 + 1];
            int h  = c0 >> 6;
            int dh = c0 & 63;
            #pragma unroll
            for (int rr = 0; rr < 2; rr++) {
                int row = r0 + rr * 8;
                int b  = row >> 11;
                int s  = row & 2047;
                size_t o = (size_t)((b * NH + h) * S_ + s) * DH + dh;
                *(float2*)&outQ[o] = make_float2(aq[mt][nt][rr * 2] + bbq0,
                                                 aq[mt][nt][rr * 2 + 1] + bbq1);
                *(float2*)&outK[o] = make_float2(ak[mt][nt][rr * 2] + bbk0,
                                                 ak[mt][nt][rr * 2 + 1] + bbk1);
            }
        }
    }
}

// ---------------------------------------------------------------------------
// Flash attention. CTA: 128 queries, 4 warps, 64-key tiles.
// QK^T: plain tf32 (Q pre-scaled). PV: bf16 2-term split via m16n8k16
// (C-frag IS the bf16 A-frag layout; P never touches smem).
// Restructured mt-innermost: K and V B-fragments loaded ONCE per (ks/ts),
// shared across both m-tiles (s kept for both: s[2][8][4]).
// smem: Qs[128][68] f32, Ks[64][68] f32, Vh32/Vl32 [32][72] u32 = 70656 B.
// ---------------------------------------------------------------------------
#define FLASH_SMEM ((128*68 + 64*68 + 2*32*72) * 4)   // 70656 bytes

__global__ __launch_bounds__(128) void flash_mma()
{
    extern __shared__ float sm[];
    float*    Qs   = sm;                          // [128][68]  q-major (tf32)
    float*    Ks   = Qs + 128 * 68;               // [64][68]   key-major (tf32)
    uint32_t* Vh32 = (uint32_t*)(Ks + 64 * 68);   // [32][72] bf16x2 key pairs
    uint32_t* Vl32 = Vh32 + 32 * 72;

    const int t    = threadIdx.x;
    const int lane = t & 31;
    const int wid  = t >> 5;         // 0..3
    const int g    = lane >> 2;
    const int q4   = lane & 3;
    const int q0   = blockIdx.x * 128;
    const int bh   = blockIdx.y;

    const float* __restrict__ Qb = g_Q + (size_t)bh * S_ * DH;
    const float* __restrict__ Kb = g_K + (size_t)bh * S_ * DH;
    const float* __restrict__ Vb = g_V + (size_t)bh * S_ * DH;

    // Load Q tile (pre-scaled, tf32), [q][dh]
    #pragma unroll
    for (int i = 0; i < 16; i++) {
        int e  = t + i * 128;
        int m  = e >> 4;
        int dq = e & 15;
        float4 v = *(const float4*)&Qb[(size_t)(q0 + m) * DH + dq * 4];
        *(float4*)&Qs[m * 68 + dq * 4] =
            make_float4(to_tf32(v.x * SCALE), to_tf32(v.y * SCALE),
                        to_tf32(v.z * SCALE), to_tf32(v.w * SCALE));
    }

    float o[2][8][4] = {};
    float mr[2][2], lr[2][2];
    #pragma unroll
    for (int mt = 0; mt < 2; mt++) {
        mr[mt][0] = -1e30f; mr[mt][1] = -1e30f;
        lr[mt][0] = 0.0f;   lr[mt][1] = 0.0f;
    }
    __syncthreads();

    const bool hihalf = (lane >= 16);   // holds odd key in V load pairing

    for (int kt = 0; kt < S_; kt += 64) {
        __syncthreads();   // all warps done reading K/V of previous tile

        // Load K (tf32, [key][dh]); V -> bf16 hi/lo, packed pairs along key.
        #pragma unroll
        for (int i = 0; i < 8; i++) {
            int e  = t + i * 128;
            int m  = e >> 4;
            int dq = e & 15;
            int d  = dq * 4;
            float4 k4 = *(const float4*)&Kb[(size_t)(kt + m) * DH + d];
            *(float4*)&Ks[m * 68 + d] =
                make_float4(to_tf32(k4.x), to_tf32(k4.y), to_tf32(k4.z), to_tf32(k4.w));

            float4 v4 = *(const float4*)&Vb[(size_t)(kt + m) * DH + d];
            float hv[4], lv[4];
            hv[0] = bfr(v4.x); lv[0] = v4.x - hv[0];
            hv[1] = bfr(v4.y); lv[1] = v4.y - hv[1];
            hv[2] = bfr(v4.z); lv[2] = v4.z - hv[2];
            hv[3] = bfr(v4.w); lv[3] = v4.w - hv[3];
            uint32_t hp[4], lp[4];
            #pragma unroll
            for (int j = 0; j < 4; j++) {
                float oh = __shfl_xor_sync(0xffffffffu, hv[j], 16);
                float ol = __shfl_xor_sync(0xffffffffu, lv[j], 16);
                hp[j] = hihalf ? packbf(oh, hv[j]) : packbf(hv[j], oh);
                lp[j] = hihalf ? packbf(ol, lv[j]) : packbf(lv[j], ol);
            }
            int kp = m >> 1;
            int jb = hihalf ? 2 : 0;
            Vh32[kp * 72 + d + jb]     = hp[jb];
            Vh32[kp * 72 + d + jb + 1] = hp[jb + 1];
            Vl32[kp * 72 + d + jb]     = lp[jb];
            Vl32[kp * 72 + d + jb + 1] = lp[jb + 1];
        }
        __syncthreads();

        // ---- QK^T, both m-tiles; K B-fragments loaded once
        float s[2][8][4] = {};
        #pragma unroll
        for (int ks = 0; ks < DH; ks += 8) {
            float a[2][4];
            #pragma unroll
            for (int mt = 0; mt < 2; mt++) {
                int rb = wid * 32 + mt * 16;
                a[mt][0] = Qs[(rb + g) * 68 + ks + q4];
                a[mt][1] = Qs[(rb + g + 8) * 68 + ks + q4];
                a[mt][2] = Qs[(rb + g) * 68 + ks + q4 + 4];
                a[mt][3] = Qs[(rb + g + 8) * 68 + ks + q4 + 4];
            }
            #pragma unroll
            for (int nt = 0; nt < 8; nt++) {
                float b[2] = { Ks[(nt * 8 + g) * 68 + ks + q4],
                               Ks[(nt * 8 + g) * 68 + ks + q4 + 4] };
                #pragma unroll
                for (int mt = 0; mt < 2; mt++)
                    mma8(s[mt][nt], a[mt], b);
            }
        }

        // ---- online softmax per m-tile
        #pragma unroll
        for (int mt = 0; mt < 2; mt++) {
            float rm0 = -1e30f, rm1 = -1e30f;
            #pragma unroll
            for (int nt = 0; nt < 8; nt++) {
                rm0 = fmaxf(rm0, fmaxf(s[mt][nt][0], s[mt][nt][1]));
                rm1 = fmaxf(rm1, fmaxf(s[mt][nt][2], s[mt][nt][3]));
            }
            rm0 = fmaxf(rm0, __shfl_xor_sync(0xffffffffu, rm0, 1));
            rm0 = fmaxf(rm0, __shfl_xor_sync(0xffffffffu, rm0, 2));
            rm1 = fmaxf(rm1, __shfl_xor_sync(0xffffffffu, rm1, 1));
            rm1 = fmaxf(rm1, __shfl_xor_sync(0xffffffffu, rm1, 2));
            float nm0 = fmaxf(mr[mt][0], rm0), nm1 = fmaxf(mr[mt][1], rm1);
            float cr0 = __expf(mr[mt][0] - nm0), cr1 = __expf(mr[mt][1] - nm1);
            float sum0 = 0.0f, sum1 = 0.0f;
            #pragma unroll
            for (int nt = 0; nt < 8; nt++) {
                s[mt][nt][0] = __expf(s[mt][nt][0] - nm0); sum0 += s[mt][nt][0];
                s[mt][nt][1] = __expf(s[mt][nt][1] - nm0); sum0 += s[mt][nt][1];
                s[mt][nt][2] = __expf(s[mt][nt][2] - nm1); sum1 += s[mt][nt][2];
                s[mt][nt][3] = __expf(s[mt][nt][3] - nm1); sum1 += s[mt][nt][3];
            }
            sum0 += __shfl_xor_sync(0xffffffffu, sum0, 1);
            sum0 += __shfl_xor_sync(0xffffffffu, sum0, 2);
            sum1 += __shfl_xor_sync(0xffffffffu, sum1, 1);
            sum1 += __shfl_xor_sync(0xffffffffu, sum1, 2);
            lr[mt][0] = lr[mt][0] * cr0 + sum0;  mr[mt][0] = nm0;
            lr[mt][1] = lr[mt][1] * cr1 + sum1;  mr[mt][1] = nm1;
            #pragma unroll
            for (int nt = 0; nt < 8; nt++) {
                o[mt][nt][0] *= cr0; o[mt][nt][1] *= cr0;
                o[mt][nt][2] *= cr1; o[mt][nt][3] *= cr1;
            }
        }

        // ---- PV: bf16 split; V B-fragments loaded once, shared across mt
        #pragma unroll
        for (int ts = 0; ts < 4; ts++) {
            uint32_t ph[2][4], pl[2][4];
            #pragma unroll
            for (int mt = 0; mt < 2; mt++) {
                float p00 = s[mt][2*ts][0],   p01 = s[mt][2*ts][1];
                float p10 = s[mt][2*ts][2],   p11 = s[mt][2*ts][3];
                float p20 = s[mt][2*ts+1][0], p21 = s[mt][2*ts+1][1];
                float p30 = s[mt][2*ts+1][2], p31 = s[mt][2*ts+1][3];
                float h00 = bfr(p00), h01 = bfr(p01);
                float h10 = bfr(p10), h11 = bfr(p11);
                float h20 = bfr(p20), h21 = bfr(p21);
                float h30 = bfr(p30), h31 = bfr(p31);
                ph[mt][0] = packbf(h00, h01); ph[mt][1] = packbf(h10, h11);
                ph[mt][2] = packbf(h20, h21); ph[mt][3] = packbf(h30, h31);
                pl[mt][0] = packbf(p00 - h00, p01 - h01);
                pl[mt][1] = packbf(p10 - h10, p11 - h11);
                pl[mt][2] = packbf(p20 - h20, p21 - h21);
                pl[mt][3] = packbf(p30 - h30, p31 - h31);
            }
            const uint32_t* vhr0 = Vh32 + (ts * 8 + q4) * 72;
            const uint32_t* vhr1 = Vh32 + (ts * 8 + 4 + q4) * 72;
            const uint32_t* vlr0 = Vl32 + (ts * 8 + q4) * 72;
            const uint32_t* vlr1 = Vl32 + (ts * 8 + 4 + q4) * 72;
            #pragma unroll
            for (int nt = 0; nt < 8; nt++) {
                int c = nt * 8 + g;
                uint32_t bh[2] = { vhr0[c], vhr1[c] };
                uint32_t bl[2] = { vlr0[c], vlr1[c] };
                #pragma unroll
                for (int mt = 0; mt < 2; mt++) {
                    mma16(o[mt][nt], ph[mt], bh);
                    mma16(o[mt][nt], ph[mt], bl);
                    mma16(o[mt][nt], pl[mt], bh);
                }
            }
        }
    }

    // Epilogue: normalize, write merged-head layout [b, s, h*64 + dh]
    const int b = bh >> 3;
    const int h = bh & 7;
    #pragma unroll
    for (int mt = 0; mt < 2; mt++) {
        int rb = wid * 32 + mt * 16;
        float inv0 = 1.0f / lr[mt][0], inv1 = 1.0f / lr[mt][1];
        #pragma unroll
        for (int nt = 0; nt < 8; nt++) {
            int col = h * DH + nt * 8 + q4 * 2;
            int qr0 = q0 + rb + g;
            *(float2*)&g_att[(size_t)(b * S_ + qr0) * DM + col] =
                make_float2(o[mt][nt][0] * inv0, o[mt][nt][1] * inv0);
            int qr1 = q0 + rb + g + 8;
            *(float2*)&g_att[(size_t)(b * S_ + qr1) * DM + col] =
                make_float2(o[mt][nt][2] * inv1, o[mt][nt][3] * inv1);
        }
    }
}

// ---------------------------------------------------------------------------
extern "C" void kernel_launch(void* const* d_in, const int* in_sizes, int n_in,
                              void* d_out, int out_size)
{
    const float* x  = (const float*)d_in[0];
    const float* Wq = (const float*)d_in[1];
    const float* bq = (const float*)d_in[2];
    const float* Wk = (const float*)d_in[3];
    const float* bk = (const float*)d_in[4];
    const float* Wv = (const float*)d_in[5];
    const float* bv = (const float*)d_in[6];
    const float* Wo = (const float*)d_in[7];
    const float* bo = (const float*)d_in[8];
    float* out = (float*)d_out;

    void *pQ, *pK, *pV, *pA;
    cudaGetSymbolAddress(&pQ, g_Q);
    cudaGetSymbolAddress(&pK, g_K);
    cudaGetSymbolAddress(&pV, g_V);
    cudaGetSymbolAddress(&pA, g_att);

    cudaFuncSetAttribute(qk_gemm,
                         cudaFuncAttributeMaxDynamicSharedMemorySize, QK_SMEM);
    cudaFuncSetAttribute(bf_gemm<true>,
                         cudaFuncAttributeMaxDynamicSharedMemorySize, BF_SMEM);
    cudaFuncSetAttribute(bf_gemm<false>,
                         cudaFuncAttributeMaxDynamicSharedMemorySize, BF_SMEM);
    cudaFuncSetAttribute(flash_mma,
                         cudaFuncAttributeMaxDynamicSharedMemorySize, FLASH_SMEM);

    dim3 ggrid(DM / 64, (B_ * S_) / 128);   // (8, 64)

    // Q+K projections fused, plain tf32 (score-path error softmax-attenuated)
    qk_gemm<<<ggrid, 256, QK_SMEM>>>(x, Wq, bq, Wk, bk, (float*)pQ, (float*)pK);
    // V projection: bf16 2-term split
    bf_gemm<true><<<ggrid, 256, BF_SMEM>>>(x, Wv, bv, (float*)pV);

    flash_mma<<<dim3(S_ / 128, B_ * NH), 128, FLASH_SMEM>>>();

    // Output projection: bf16 2-term split
    bf_gemm<false><<<ggrid, 256, BF_SMEM>>>((const float*)pA, Wo, bo, out);
}